// round 5
// baseline (speedup 1.0000x reference)
#include <cuda_runtime.h>
#include <cuda_bf16.h>
#include <cstdint>
#include <math.h>
#include <float.h>

// Problem constants
#define BATCH 8
#define SEQ   2048
#define DMODEL 1024
#define EPS_ENT 1e-10f
#define EPS_LN  1e-5f

// ---------------- scratch (allocation-free: __device__ globals) ----------------
__device__ float g_scores[(size_t)BATCH * SEQ * SEQ];     // 134 MB
__device__ float g_attout[(size_t)BATCH * SEQ * DMODEL];  // 67 MB
__device__ float g_rowent[(size_t)BATCH * SEQ];

// ---------------- tf32 helpers ----------------
__device__ __forceinline__ float to_tf32(float x) {
    uint32_t r;
    asm("cvt.rna.tf32.f32 %0, %1;" : "=r"(r) : "f"(x));
    return __uint_as_float(r);
}
__device__ __forceinline__ void mma_tf32(float c[4], const uint32_t a[4], const uint32_t b[2]) {
    asm volatile(
        "mma.sync.aligned.m16n8k8.row.col.f32.tf32.tf32.f32 "
        "{%0,%1,%2,%3}, {%4,%5,%6,%7}, {%8,%9}, {%0,%1,%2,%3};"
        : "+f"(c[0]), "+f"(c[1]), "+f"(c[2]), "+f"(c[3])
        : "r"(a[0]), "r"(a[1]), "r"(a[2]), "r"(a[3]), "r"(b[0]), "r"(b[1]));
}

// =====================================================================
// tf32 mma.sync GEMM:  C[M,N] = alpha * A[M,K] @ op(B) (+ bias)
//   TB=true : B is [N,K] row-major (C = A @ B^T)
//   TB=false: B is [K,N] row-major (C = A @ B)
// Block tile 128x128, BK=32, 512 threads = 16 warps (4 M x 4 N),
// warp tile 32x32 (2 m16 x 4 n8). Double-buffered SMEM, LDK=36 pad
// -> fragment loads hit banks (4g+t) mod 32, all distinct.
// =====================================================================
#define BM 128
#define BN 128
#define BKK 32
#define LDK 36                         // floats per SMEM row (32 + 4 pad)
#define TILE_F (128 * LDK)             // 4608 floats per tile
#define NTHR 512

template <bool TB, bool BIAS>
__global__ __launch_bounds__(NTHR, 1) void mma_gemm_kernel(
    const float* __restrict__ Ag, const float* __restrict__ Bg,
    const float* __restrict__ bias, float* __restrict__ Cg,
    int K, long lda, long ldb, long ldc,
    long sA, long sB, long sC, float alpha)
{
    extern __shared__ float sm[];   // [A0 B0 A1 B1], each TILE_F floats

    const int tid = threadIdx.x;
    const int wid = tid >> 5;
    const int lid = tid & 31;
    const int wm = wid & 3;          // warp M position (0..3)
    const int wn = wid >> 2;         // warp N position (0..3)
    const int g = lid >> 2;          // group id (0..7)
    const int t = lid & 3;           // thread-in-group (0..3)

    const long bm = (long)blockIdx.x * BM;
    const long bn = (long)blockIdx.y * BN;
    const float* A = Ag + (long)blockIdx.z * sA;
    const float* B = Bg + (long)blockIdx.z * sB;
    float* C = Cg + (long)blockIdx.z * sC;

    float acc[2][4][4];
#pragma unroll
    for (int mt = 0; mt < 2; ++mt)
#pragma unroll
        for (int nt = 0; nt < 4; ++nt)
#pragma unroll
            for (int c = 0; c < 4; ++c) acc[mt][nt][c] = 0.0f;

    float4 ra[2], rb[2];

    // ---- gmem -> regs for chunk at k0 ----
    auto load_regs = [&](long k0) {
#pragma unroll
        for (int it = 0; it < 2; ++it) {
            int slot = tid + it * NTHR;    // A: 128 rows x 8 float4 along k (1024 slots)
            ra[it] = *(const float4*)&A[(bm + (slot >> 3)) * lda + k0 + ((slot & 7) << 2)];
        }
        if (TB) {
#pragma unroll
            for (int it = 0; it < 2; ++it) {
                int slot = tid + it * NTHR; // B: 128 rows (n) x 8 float4 (k)
                rb[it] = *(const float4*)&B[(bn + (slot >> 3)) * ldb + k0 + ((slot & 7) << 2)];
            }
        } else {
            // B is [K,N]; gather 4 k-rows per lane (each row access 128B-coalesced per warp)
#pragma unroll
            for (int it = 0; it < 2; ++it) {
                int slot = tid + it * NTHR;
                int n = slot & 127;
                int kq = slot >> 7;        // 0..7
                const float* bp = &B[(k0 + kq * 4) * ldb + bn + n];
                rb[it].x = bp[0];
                rb[it].y = bp[ldb];
                rb[it].z = bp[2 * ldb];
                rb[it].w = bp[3 * ldb];
            }
        }
    };

    // ---- regs -> smem stage (tf32 rounding; STS.128, conflict-free) ----
    auto store_regs = [&](int s) {
        float* As_ = sm + s * 2 * TILE_F;
        float* Bs_ = As_ + TILE_F;
#pragma unroll
        for (int it = 0; it < 2; ++it) {
            int slot = tid + it * NTHR;
            int m = slot >> 3, k4 = (slot & 7) << 2;
            float4 v;
            v.x = to_tf32(ra[it].x); v.y = to_tf32(ra[it].y);
            v.z = to_tf32(ra[it].z); v.w = to_tf32(ra[it].w);
            *(float4*)&As_[m * LDK + k4] = v;
        }
        if (TB) {
#pragma unroll
            for (int it = 0; it < 2; ++it) {
                int slot = tid + it * NTHR;
                int n = slot >> 3, k4 = (slot & 7) << 2;
                float4 v;
                v.x = to_tf32(rb[it].x); v.y = to_tf32(rb[it].y);
                v.z = to_tf32(rb[it].z); v.w = to_tf32(rb[it].w);
                *(float4*)&Bs_[n * LDK + k4] = v;
            }
        } else {
#pragma unroll
            for (int it = 0; it < 2; ++it) {
                int slot = tid + it * NTHR;
                int n = slot & 127, k4 = (slot >> 7) << 2;
                float4 v;
                v.x = to_tf32(rb[it].x); v.y = to_tf32(rb[it].y);
                v.z = to_tf32(rb[it].z); v.w = to_tf32(rb[it].w);
                *(float4*)&Bs_[n * LDK + k4] = v;
            }
        }
    };

    // ---- compute one BK=32 chunk from smem stage ----
    auto compute = [&](int s) {
        const float* As_ = sm + s * 2 * TILE_F;
        const float* Bs_ = As_ + TILE_F;
#pragma unroll
        for (int ks = 0; ks < 4; ++ks) {
            const int kb = ks * 8;
            uint32_t a[2][4], b[4][2];
#pragma unroll
            for (int mt = 0; mt < 2; ++mt) {
                const int m0 = wm * 32 + mt * 16;
                a[mt][0] = __float_as_uint(As_[(m0 + g) * LDK + kb + t]);
                a[mt][1] = __float_as_uint(As_[(m0 + g + 8) * LDK + kb + t]);
                a[mt][2] = __float_as_uint(As_[(m0 + g) * LDK + kb + t + 4]);
                a[mt][3] = __float_as_uint(As_[(m0 + g + 8) * LDK + kb + t + 4]);
            }
#pragma unroll
            for (int nt = 0; nt < 4; ++nt) {
                const int n0 = wn * 32 + nt * 8;
                b[nt][0] = __float_as_uint(Bs_[(n0 + g) * LDK + kb + t]);
                b[nt][1] = __float_as_uint(Bs_[(n0 + g) * LDK + kb + t + 4]);
            }
#pragma unroll
            for (int mt = 0; mt < 2; ++mt)
#pragma unroll
                for (int nt = 0; nt < 4; ++nt)
                    mma_tf32(acc[mt][nt], a[mt], b[nt]);
        }
    };

    const int nch = K / BKK;
    load_regs(0);
    store_regs(0);
    __syncthreads();
    for (int i = 0; i < nch; ++i) {
        const int s = i & 1;
        if (i + 1 < nch) load_regs((long)(i + 1) * BKK);
        compute(s);
        __syncthreads();
        if (i + 1 < nch) {
            store_regs(s ^ 1);
            __syncthreads();
        }
    }

    // ---- epilogue ----
#pragma unroll
    for (int mt = 0; mt < 2; ++mt) {
        const long mrow = bm + wm * 32 + mt * 16;
#pragma unroll
        for (int nt = 0; nt < 4; ++nt) {
            const long col = bn + wn * 32 + nt * 8 + 2 * t;
            float2 v0, v1;
            v0.x = acc[mt][nt][0] * alpha; v0.y = acc[mt][nt][1] * alpha;
            v1.x = acc[mt][nt][2] * alpha; v1.y = acc[mt][nt][3] * alpha;
            if (BIAS) {
                float b0 = bias[col], b1 = bias[col + 1];
                v0.x += b0; v0.y += b1; v1.x += b0; v1.y += b1;
            }
            *(float2*)&C[(mrow + g) * ldc + col] = v0;
            *(float2*)&C[(mrow + g + 8) * ldc + col] = v1;
        }
    }
}

#define GEMM_SMEM_BYTES (4 * TILE_F * sizeof(float))   // 73728

// =====================================================================
// reductions + softmax/entropy + syntony + layernorm
// =====================================================================
__device__ __forceinline__ float warpReduceSum(float v) {
#pragma unroll
    for (int o = 16; o > 0; o >>= 1) v += __shfl_xor_sync(0xffffffffu, v, o);
    return v;
}
__device__ __forceinline__ float warpReduceMax(float v) {
#pragma unroll
    for (int o = 16; o > 0; o >>= 1) v = fmaxf(v, __shfl_xor_sync(0xffffffffu, v, o));
    return v;
}
__device__ __forceinline__ float blockReduceSum(float v) {
    __shared__ float sh[32];
    int lane = threadIdx.x & 31, w = threadIdx.x >> 5;
    v = warpReduceSum(v);
    if (lane == 0) sh[w] = v;
    __syncthreads();
    int nw = (blockDim.x + 31) >> 5;
    float r = (threadIdx.x < nw) ? sh[threadIdx.x] : 0.0f;
    if (w == 0) r = warpReduceSum(r);
    if (threadIdx.x == 0) sh[0] = r;
    __syncthreads();
    float out = sh[0];
    __syncthreads();
    return out;
}
__device__ __forceinline__ float blockReduceMax(float v) {
    __shared__ float sh[32];
    int lane = threadIdx.x & 31, w = threadIdx.x >> 5;
    v = warpReduceMax(v);
    if (lane == 0) sh[w] = v;
    __syncthreads();
    int nw = (blockDim.x + 31) >> 5;
    float r = (threadIdx.x < nw) ? sh[threadIdx.x] : -FLT_MAX;
    if (w == 0) r = warpReduceMax(r);
    if (threadIdx.x == 0) sh[0] = r;
    __syncthreads();
    float out = sh[0];
    __syncthreads();
    return out;
}

__global__ __launch_bounds__(256) void softmax_entropy_kernel() {
    const long row = blockIdx.x;
    float* p = g_scores + row * (long)SEQ;
    const int tid = threadIdx.x;
    float x[8];
#pragma unroll
    for (int i = 0; i < 8; ++i) x[i] = p[tid + i * 256];
    float m = -FLT_MAX;
#pragma unroll
    for (int i = 0; i < 8; ++i) m = fmaxf(m, x[i]);
    m = blockReduceMax(m);
    float s = 0.0f;
#pragma unroll
    for (int i = 0; i < 8; ++i) { x[i] = expf(x[i] - m); s += x[i]; }
    s = blockReduceSum(s);
    float inv = 1.0f / s;
    float ent = 0.0f;
#pragma unroll
    for (int i = 0; i < 8; ++i) {
        float pv = x[i] * inv;
        p[tid + i * 256] = pv;
        ent -= pv * logf(pv + EPS_ENT);
    }
    ent = blockReduceSum(ent);
    if (tid == 0) g_rowent[row] = ent;
}

__global__ __launch_bounds__(512) void syntony_kernel(float* __restrict__ out, long tail_off, int tail_cnt) {
    float s = 0.0f;
    const int nrows = BATCH * SEQ;
    for (int i = threadIdx.x; i < nrows; i += 512) s += g_rowent[i];
    s = blockReduceSum(s);
    if (threadIdx.x == 0) {
        float mean = s / (float)nrows;
        float syn = 1.0f - mean / logf((float)SEQ);
        syn = fminf(fmaxf(syn, 0.0f), 1.0f);
        for (int i = 0; i < tail_cnt; ++i) out[tail_off + i] = syn;
    }
}

__global__ __launch_bounds__(256) void layernorm_kernel(
    float* __restrict__ H, const float* __restrict__ gamma, const float* __restrict__ beta)
{
    const long row = blockIdx.x;
    float* h = H + row * (long)DMODEL;
    const int tid = threadIdx.x;
    float x[4];
#pragma unroll
    for (int i = 0; i < 4; ++i) x[i] = h[tid + i * 256];
    float s = x[0] + x[1] + x[2] + x[3];
    s = blockReduceSum(s);
    float mu = s * (1.0f / DMODEL);
    float v = 0.0f;
#pragma unroll
    for (int i = 0; i < 4; ++i) { float d = x[i] - mu; v += d * d; }
    v = blockReduceSum(v);
    float inv = rsqrtf(v * (1.0f / DMODEL) + EPS_LN);
#pragma unroll
    for (int i = 0; i < 4; ++i) {
        int c = tid + i * 256;
        h[c] = (x[i] - mu) * inv * gamma[c] + beta[c];
    }
}

// =====================================================================
// launch
// =====================================================================
extern "C" void kernel_launch(void* const* d_in, const int* in_sizes, int n_in,
                              void* d_out, int out_size) {
    const float* q      = (const float*)d_in[0];
    const float* k      = (const float*)d_in[1];
    const float* v      = (const float*)d_in[2];
    const float* harm_w = (const float*)d_in[3];
    const float* harm_b = (const float*)d_in[4];
    const float* gamma  = (const float*)d_in[5];
    const float* beta   = (const float*)d_in[6];
    float* out = (float*)d_out;

    float *scores, *attout;
    cudaGetSymbolAddress((void**)&scores, g_scores);
    cudaGetSymbolAddress((void**)&attout, g_attout);

    cudaFuncSetAttribute(mma_gemm_kernel<true, false>,  cudaFuncAttributeMaxDynamicSharedMemorySize, GEMM_SMEM_BYTES);
    cudaFuncSetAttribute(mma_gemm_kernel<false, false>, cudaFuncAttributeMaxDynamicSharedMemorySize, GEMM_SMEM_BYTES);
    cudaFuncSetAttribute(mma_gemm_kernel<false, true>,  cudaFuncAttributeMaxDynamicSharedMemorySize, GEMM_SMEM_BYTES);

    const long sQK = (long)SEQ * DMODEL;
    const long sS  = (long)SEQ * SEQ;
    const long BSD = (long)BATCH * SEQ * DMODEL;

    // 1) scores = (Q @ K^T) / 32
    {
        dim3 grid(SEQ / BM, SEQ / BN, BATCH);
        mma_gemm_kernel<true, false><<<grid, NTHR, GEMM_SMEM_BYTES>>>(
            q, k, nullptr, scores, DMODEL, DMODEL, DMODEL, SEQ, sQK, sQK, sS, 1.0f / 32.0f);
    }
    // 2) softmax + row entropy (in-place)
    softmax_entropy_kernel<<<BATCH * SEQ, 256>>>();
    // 3) syntony scalar -> tail of d_out
    {
        int tail = (int)((long)out_size - BSD);
        if (tail > 0) syntony_kernel<<<1, 512>>>(out, BSD, tail);
    }
    // 4) attout = P @ V   (B = V is [K=SEQ, N=DMODEL])
    {
        dim3 grid(SEQ / BM, DMODEL / BN, BATCH);
        mma_gemm_kernel<false, false><<<grid, NTHR, GEMM_SMEM_BYTES>>>(
            scores, v, nullptr, attout, SEQ, SEQ, DMODEL, DMODEL, sS, sQK, sQK, 1.0f);
    }
    // 5) h = attout @ W + b   (B = W is [K=DMODEL, N=DMODEL]) -> d_out
    {
        dim3 grid((BATCH * SEQ) / BM, DMODEL / BN, 1);
        mma_gemm_kernel<false, true><<<grid, NTHR, GEMM_SMEM_BYTES>>>(
            attout, harm_w, harm_b, out, DMODEL, DMODEL, DMODEL, DMODEL, 0L, 0L, 0L, 1.0f);
    }
    // 6) layernorm in-place on d_out
    layernorm_kernel<<<BATCH * SEQ, 256>>>(out, gamma, beta);
}

// round 6
// speedup vs baseline: 1.2258x; 1.2258x over previous
#include <cuda_runtime.h>
#include <cuda_bf16.h>
#include <cstdint>
#include <math.h>
#include <float.h>

// Problem constants
#define BATCH 8
#define SEQ   2048
#define DMODEL 1024
#define EPS_ENT 1e-10f
#define EPS_LN  1e-5f

// ---------------- scratch (allocation-free: __device__ globals) ----------------
__device__ float g_scores[(size_t)BATCH * SEQ * SEQ];     // 134 MB
__device__ float g_attout[(size_t)BATCH * SEQ * DMODEL];  // 67 MB
__device__ float g_q[(size_t)BATCH * SEQ * DMODEL];       // 67 MB  rounded Q
__device__ float g_k[(size_t)BATCH * SEQ * DMODEL];       // 67 MB  rounded K
__device__ float g_vt[(size_t)BATCH * DMODEL * SEQ];      // 67 MB  rounded V^T
__device__ float g_wt[(size_t)DMODEL * DMODEL];           // 4 MB   rounded W^T
__device__ float g_rowent[(size_t)BATCH * SEQ];

// ---------------- tf32 / async helpers ----------------
__device__ __forceinline__ float to_tf32(float x) {
    uint32_t r;
    asm("cvt.rna.tf32.f32 %0, %1;" : "=r"(r) : "f"(x));
    return __uint_as_float(r);
}
__device__ __forceinline__ void mma_tf32(float c[4], const uint32_t a[4], const uint32_t b[2]) {
    asm volatile(
        "mma.sync.aligned.m16n8k8.row.col.f32.tf32.tf32.f32 "
        "{%0,%1,%2,%3}, {%4,%5,%6,%7}, {%8,%9}, {%0,%1,%2,%3};"
        : "+f"(c[0]), "+f"(c[1]), "+f"(c[2]), "+f"(c[3])
        : "r"(a[0]), "r"(a[1]), "r"(a[2]), "r"(a[3]), "r"(b[0]), "r"(b[1]));
}
__device__ __forceinline__ uint32_t smem_u32(const void* p) {
    uint32_t a;
    asm("{ .reg .u64 t; cvta.to.shared.u64 t, %1; cvt.u32.u64 %0, t; }" : "=r"(a) : "l"(p));
    return a;
}
#define CP_ASYNC16(dst, src) \
    asm volatile("cp.async.cg.shared.global [%0], [%1], 16;" :: "r"(dst), "l"(src))
#define CP_COMMIT() asm volatile("cp.async.commit_group;" ::: "memory")
#define CP_WAIT0()  asm volatile("cp.async.wait_group 0;" ::: "memory")
#define CP_WAIT1()  asm volatile("cp.async.wait_group 1;" ::: "memory")

// =====================================================================
// tf32 mma.sync GEMM (all operands pre-rounded to tf32):
//   C[M,N] = alpha * A[M,K] @ B[N,K]^T (+ bias) [, round output to tf32]
// Block tile 128x256, BK=32, 256 threads = 8 warps (2 M x 4 N),
// warp tile 64x64 (4 m16 x 8 n8). 3-stage cp.async pipeline.
// SMEM tiles [row][k], LDK=36 pad -> all fragment LDS conflict-free.
// =====================================================================
#define BM 128
#define BN 256
#define BKK 32
#define LDK 36
#define A_TILE_F (128 * LDK)               // 4608 floats
#define B_TILE_F (256 * LDK)               // 9216 floats
#define STAGE_F  (A_TILE_F + B_TILE_F)     // 13824 floats
#define NSTAGE 3
#define GEMM_SMEM_BYTES (NSTAGE * STAGE_F * 4)   // 165888

template <bool BIAS, bool ROUND_OUT>
__global__ __launch_bounds__(256, 1) void gemm_kernel(
    const float* __restrict__ Ag, const float* __restrict__ Bg,
    const float* __restrict__ bias, float* __restrict__ Cg,
    int K, long lda, long ldb, long ldc,
    long sA, long sB, long sC, float alpha)
{
    extern __shared__ float sm[];

    const int tid = threadIdx.x;
    const int wid = tid >> 5;
    const int lid = tid & 31;
    const int wm = wid & 1;          // warp M position (0..1)
    const int wn = wid >> 1;         // warp N position (0..3)
    const int g = lid >> 2;          // 0..7
    const int t = lid & 3;           // 0..3

    const long bm = (long)blockIdx.x * BM;
    const long bn = (long)blockIdx.y * BN;
    const float* A = Ag + (long)blockIdx.z * sA;
    const float* B = Bg + (long)blockIdx.z * sB;
    float* C = Cg + (long)blockIdx.z * sC;

    const uint32_t sbase = smem_u32(sm);

    float acc[4][8][4];
#pragma unroll
    for (int mt = 0; mt < 4; ++mt)
#pragma unroll
        for (int nt = 0; nt < 8; ++nt)
#pragma unroll
            for (int c = 0; c < 4; ++c) acc[mt][nt][c] = 0.0f;

    // ---- issue cp.async copies for one BK chunk into stage s ----
    auto copy_stage = [&](int s, long k0) {
        const uint32_t as = sbase + (uint32_t)(s * STAGE_F) * 4u;
        const uint32_t bs = as + (uint32_t)A_TILE_F * 4u;
#pragma unroll
        for (int it = 0; it < 4; ++it) {
            int c = tid + it * 256;              // 1024 chunks: A 128 rows x 8
            int m = c >> 3, k4 = (c & 7) << 2;
            CP_ASYNC16(as + (uint32_t)(m * LDK + k4) * 4u,
                       &A[(bm + m) * lda + k0 + k4]);
        }
#pragma unroll
        for (int it = 0; it < 8; ++it) {
            int c = tid + it * 256;              // 2048 chunks: B 256 rows x 8
            int n = c >> 3, k4 = (c & 7) << 2;
            CP_ASYNC16(bs + (uint32_t)(n * LDK + k4) * 4u,
                       &B[(bn + n) * ldb + k0 + k4]);
        }
    };

    // ---- compute one BK=32 chunk from stage s ----
    auto compute = [&](int s) {
        const float* As_ = sm + s * STAGE_F;
        const float* Bs_ = As_ + A_TILE_F;
#pragma unroll
        for (int ks = 0; ks < 4; ++ks) {
            const int kb = ks * 8;
            uint32_t a[4][4], b[8][2];
#pragma unroll
            for (int mt = 0; mt < 4; ++mt) {
                const int m0 = wm * 64 + mt * 16;
                a[mt][0] = __float_as_uint(As_[(m0 + g) * LDK + kb + t]);
                a[mt][1] = __float_as_uint(As_[(m0 + g + 8) * LDK + kb + t]);
                a[mt][2] = __float_as_uint(As_[(m0 + g) * LDK + kb + t + 4]);
                a[mt][3] = __float_as_uint(As_[(m0 + g + 8) * LDK + kb + t + 4]);
            }
#pragma unroll
            for (int nt = 0; nt < 8; ++nt) {
                const int n0 = wn * 64 + nt * 8;
                b[nt][0] = __float_as_uint(Bs_[(n0 + g) * LDK + kb + t]);
                b[nt][1] = __float_as_uint(Bs_[(n0 + g) * LDK + kb + t + 4]);
            }
#pragma unroll
            for (int mt = 0; mt < 4; ++mt)
#pragma unroll
                for (int nt = 0; nt < 8; ++nt)
                    mma_tf32(acc[mt][nt], a[mt], b[nt]);
        }
    };

    const int nch = K / BKK;
    copy_stage(0, 0); CP_COMMIT();
    if (nch > 1) { copy_stage(1, BKK); CP_COMMIT(); }

    for (int i = 0; i < nch; ++i) {
        const int s = i % NSTAGE;
        if (i + 1 < nch) { CP_WAIT1(); } else { CP_WAIT0(); }
        __syncthreads();
        if (i + 2 < nch) { copy_stage((i + 2) % NSTAGE, (long)(i + 2) * BKK); CP_COMMIT(); }
        compute(s);
    }

    // ---- epilogue ----
#pragma unroll
    for (int mt = 0; mt < 4; ++mt) {
        const long mrow = bm + wm * 64 + mt * 16;
#pragma unroll
        for (int nt = 0; nt < 8; ++nt) {
            const long col = bn + wn * 64 + nt * 8 + 2 * t;
            float2 v0, v1;
            v0.x = acc[mt][nt][0] * alpha; v0.y = acc[mt][nt][1] * alpha;
            v1.x = acc[mt][nt][2] * alpha; v1.y = acc[mt][nt][3] * alpha;
            if (BIAS) {
                float b0 = bias[col], b1 = bias[col + 1];
                v0.x += b0; v0.y += b1; v1.x += b0; v1.y += b1;
            }
            if (ROUND_OUT) {
                v0.x = to_tf32(v0.x); v0.y = to_tf32(v0.y);
                v1.x = to_tf32(v1.x); v1.y = to_tf32(v1.y);
            }
            *(float2*)&C[(mrow + g) * ldc + col] = v0;
            *(float2*)&C[(mrow + g + 8) * ldc + col] = v1;
        }
    }
}

// =====================================================================
// pre-pass: elementwise tf32 round (float4)
// =====================================================================
__global__ __launch_bounds__(256) void round4_kernel(
    const float4* __restrict__ in, float4* __restrict__ out, long n4)
{
    long i = (long)blockIdx.x * 256 + threadIdx.x;
    if (i < n4) {
        float4 v = in[i];
        v.x = to_tf32(v.x); v.y = to_tf32(v.y);
        v.z = to_tf32(v.z); v.w = to_tf32(v.w);
        out[i] = v;
    }
}

// transpose + round: out[b][c][r] = tf32(in[b][r][c])
__global__ __launch_bounds__(256) void transpose_round_kernel(
    const float* __restrict__ in, float* __restrict__ out, int R, int C, long sz)
{
    __shared__ float tbuf[32][33];
    const float* ip = in + (long)blockIdx.z * sz;
    float* op = out + (long)blockIdx.z * sz;
    int c0 = blockIdx.x * 32, r0 = blockIdx.y * 32;
    int tx = threadIdx.x, ty = threadIdx.y; // 32 x 8
#pragma unroll
    for (int j = 0; j < 32; j += 8) tbuf[ty + j][tx] = ip[(long)(r0 + ty + j) * C + c0 + tx];
    __syncthreads();
#pragma unroll
    for (int j = 0; j < 32; j += 8) op[(long)(c0 + ty + j) * R + r0 + tx] = to_tf32(tbuf[tx][ty + j]);
}

// =====================================================================
// reductions + softmax/entropy + syntony + layernorm
// =====================================================================
__device__ __forceinline__ float warpReduceSum(float v) {
#pragma unroll
    for (int o = 16; o > 0; o >>= 1) v += __shfl_xor_sync(0xffffffffu, v, o);
    return v;
}
__device__ __forceinline__ float warpReduceMax(float v) {
#pragma unroll
    for (int o = 16; o > 0; o >>= 1) v = fmaxf(v, __shfl_xor_sync(0xffffffffu, v, o));
    return v;
}
__device__ __forceinline__ float blockReduceSum(float v) {
    __shared__ float sh[32];
    int lane = threadIdx.x & 31, w = threadIdx.x >> 5;
    v = warpReduceSum(v);
    if (lane == 0) sh[w] = v;
    __syncthreads();
    int nw = (blockDim.x + 31) >> 5;
    float r = (threadIdx.x < nw) ? sh[threadIdx.x] : 0.0f;
    if (w == 0) r = warpReduceSum(r);
    if (threadIdx.x == 0) sh[0] = r;
    __syncthreads();
    float out = sh[0];
    __syncthreads();
    return out;
}
__device__ __forceinline__ float blockReduceMax(float v) {
    __shared__ float sh[32];
    int lane = threadIdx.x & 31, w = threadIdx.x >> 5;
    v = warpReduceMax(v);
    if (lane == 0) sh[w] = v;
    __syncthreads();
    int nw = (blockDim.x + 31) >> 5;
    float r = (threadIdx.x < nw) ? sh[threadIdx.x] : -FLT_MAX;
    if (w == 0) r = warpReduceMax(r);
    if (threadIdx.x == 0) sh[0] = r;
    __syncthreads();
    float out = sh[0];
    __syncthreads();
    return out;
}

__global__ __launch_bounds__(256) void softmax_entropy_kernel() {
    const long row = blockIdx.x;
    float* p = g_scores + row * (long)SEQ;
    const int tid = threadIdx.x;
    float x[8];
#pragma unroll
    for (int i = 0; i < 8; ++i) x[i] = p[tid + i * 256];
    float m = -FLT_MAX;
#pragma unroll
    for (int i = 0; i < 8; ++i) m = fmaxf(m, x[i]);
    m = blockReduceMax(m);
    float s = 0.0f;
#pragma unroll
    for (int i = 0; i < 8; ++i) { x[i] = expf(x[i] - m); s += x[i]; }
    s = blockReduceSum(s);
    float inv = 1.0f / s;
    float ent = 0.0f;
#pragma unroll
    for (int i = 0; i < 8; ++i) {
        float pv = x[i] * inv;
        p[tid + i * 256] = to_tf32(pv);   // pre-round for GEMM2's cp.async path
        ent -= pv * logf(pv + EPS_ENT);
    }
    ent = blockReduceSum(ent);
    if (tid == 0) g_rowent[row] = ent;
}

__global__ __launch_bounds__(512) void syntony_kernel(float* __restrict__ out, long tail_off, int tail_cnt) {
    float s = 0.0f;
    const int nrows = BATCH * SEQ;
    for (int i = threadIdx.x; i < nrows; i += 512) s += g_rowent[i];
    s = blockReduceSum(s);
    if (threadIdx.x == 0) {
        float mean = s / (float)nrows;
        float syn = 1.0f - mean / logf((float)SEQ);
        syn = fminf(fmaxf(syn, 0.0f), 1.0f);
        for (int i = 0; i < tail_cnt; ++i) out[tail_off + i] = syn;
    }
}

__global__ __launch_bounds__(256) void layernorm_kernel(
    float* __restrict__ H, const float* __restrict__ gamma, const float* __restrict__ beta)
{
    const long row = blockIdx.x;
    float* h = H + row * (long)DMODEL;
    const int tid = threadIdx.x;
    float x[4];
#pragma unroll
    for (int i = 0; i < 4; ++i) x[i] = h[tid + i * 256];
    float s = x[0] + x[1] + x[2] + x[3];
    s = blockReduceSum(s);
    float mu = s * (1.0f / DMODEL);
    float v = 0.0f;
#pragma unroll
    for (int i = 0; i < 4; ++i) { float d = x[i] - mu; v += d * d; }
    v = blockReduceSum(v);
    float inv = rsqrtf(v * (1.0f / DMODEL) + EPS_LN);
#pragma unroll
    for (int i = 0; i < 4; ++i) {
        int c = tid + i * 256;
        h[c] = (x[i] - mu) * inv * gamma[c] + beta[c];
    }
}

// =====================================================================
// launch
// =====================================================================
extern "C" void kernel_launch(void* const* d_in, const int* in_sizes, int n_in,
                              void* d_out, int out_size) {
    const float* q      = (const float*)d_in[0];
    const float* k      = (const float*)d_in[1];
    const float* v      = (const float*)d_in[2];
    const float* harm_w = (const float*)d_in[3];
    const float* harm_b = (const float*)d_in[4];
    const float* gamma  = (const float*)d_in[5];
    const float* beta   = (const float*)d_in[6];
    float* out = (float*)d_out;

    float *scores, *attout, *qr, *kr, *vt, *wt;
    cudaGetSymbolAddress((void**)&scores, g_scores);
    cudaGetSymbolAddress((void**)&attout, g_attout);
    cudaGetSymbolAddress((void**)&qr, g_q);
    cudaGetSymbolAddress((void**)&kr, g_k);
    cudaGetSymbolAddress((void**)&vt, g_vt);
    cudaGetSymbolAddress((void**)&wt, g_wt);

    cudaFuncSetAttribute(gemm_kernel<false, false>, cudaFuncAttributeMaxDynamicSharedMemorySize, GEMM_SMEM_BYTES);
    cudaFuncSetAttribute(gemm_kernel<false, true>,  cudaFuncAttributeMaxDynamicSharedMemorySize, GEMM_SMEM_BYTES);
    cudaFuncSetAttribute(gemm_kernel<true, false>,  cudaFuncAttributeMaxDynamicSharedMemorySize, GEMM_SMEM_BYTES);

    const long sQK = (long)SEQ * DMODEL;
    const long sS  = (long)SEQ * SEQ;
    const long BSD = (long)BATCH * SEQ * DMODEL;

    // 0) pre-round Q,K; transpose+round V,W
    {
        long n4 = BSD / 4;
        round4_kernel<<<(unsigned)((n4 + 255) / 256), 256>>>((const float4*)q, (float4*)qr, n4);
        round4_kernel<<<(unsigned)((n4 + 255) / 256), 256>>>((const float4*)k, (float4*)kr, n4);
        dim3 blk(32, 8);
        transpose_round_kernel<<<dim3(DMODEL / 32, DMODEL / 32, 1), blk>>>(harm_w, wt, DMODEL, DMODEL, 0L);
        transpose_round_kernel<<<dim3(DMODEL / 32, SEQ / 32, BATCH), blk>>>(v, vt, SEQ, DMODEL, sQK);
    }
    // 1) scores = (Q @ K^T) / 32
    {
        dim3 grid(SEQ / BM, SEQ / BN, BATCH);
        gemm_kernel<false, false><<<grid, 256, GEMM_SMEM_BYTES>>>(
            qr, kr, nullptr, scores, DMODEL, DMODEL, DMODEL, SEQ, sQK, sQK, sS, 1.0f / 32.0f);
    }
    // 2) softmax + row entropy (in-place, rounds P)
    softmax_entropy_kernel<<<BATCH * SEQ, 256>>>();
    // 3) syntony scalar -> tail of d_out
    {
        int tail = (int)((long)out_size - BSD);
        if (tail > 0) syntony_kernel<<<1, 512>>>(out, BSD, tail);
    }
    // 4) attout = P @ V  (B = V^T [D, SEQ] K-major), round output for GEMM3
    {
        dim3 grid(SEQ / BM, DMODEL / BN, BATCH);
        gemm_kernel<false, true><<<grid, 256, GEMM_SMEM_BYTES>>>(
            scores, vt, nullptr, attout, SEQ, SEQ, SEQ, DMODEL, sS, sQK, sQK, 1.0f);
    }
    // 5) h = attout @ W + b  (B = W^T [D, D] K-major) -> d_out
    {
        dim3 grid((BATCH * SEQ) / BM, DMODEL / BN, 1);
        gemm_kernel<true, false><<<grid, 256, GEMM_SMEM_BYTES>>>(
            attout, wt, harm_b, out, DMODEL, DMODEL, DMODEL, DMODEL, 0L, 0L, 0L, 1.0f);
    }
    // 6) layernorm in-place on d_out
    layernorm_kernel<<<BATCH * SEQ, 256>>>(out, gamma, beta);
}

// round 7
// speedup vs baseline: 1.8923x; 1.5437x over previous
#include <cuda_runtime.h>
#include <cuda_fp16.h>
#include <cstdint>
#include <math.h>
#include <float.h>

// Problem constants
#define BATCH 8
#define SEQ   2048
#define DMODEL 1024
#define EPS_ENT 1e-10f
#define EPS_LN  1e-5f

// ---------------- scratch (allocation-free: __device__ globals) ----------------
__device__ float  g_scores[(size_t)BATCH * SEQ * SEQ];      // 134 MB (fp32 scores)
__device__ __half g_ph[(size_t)BATCH * SEQ * SEQ];          // 67 MB  (fp16 probs)
__device__ __half g_qh[(size_t)BATCH * SEQ * DMODEL];       // 34 MB
__device__ __half g_kh[(size_t)BATCH * SEQ * DMODEL];       // 34 MB
__device__ __half g_vth[(size_t)BATCH * DMODEL * SEQ];      // 34 MB  V^T fp16
__device__ __half g_wth[(size_t)DMODEL * DMODEL];           // 2 MB   W^T fp16
__device__ __half g_aoh[(size_t)BATCH * SEQ * DMODEL];      // 34 MB  attout fp16
__device__ float  g_rowent[(size_t)BATCH * SEQ];

// ---------------- helpers ----------------
__device__ __forceinline__ void mma_f16(float c[4], const uint32_t a[4], const uint32_t b[2]) {
    asm volatile(
        "mma.sync.aligned.m16n8k16.row.col.f32.f16.f16.f32 "
        "{%0,%1,%2,%3}, {%4,%5,%6,%7}, {%8,%9}, {%0,%1,%2,%3};"
        : "+f"(c[0]), "+f"(c[1]), "+f"(c[2]), "+f"(c[3])
        : "r"(a[0]), "r"(a[1]), "r"(a[2]), "r"(a[3]), "r"(b[0]), "r"(b[1]));
}
__device__ __forceinline__ uint32_t smem_u32(const void* p) {
    uint32_t a;
    asm("{ .reg .u64 t; cvta.to.shared.u64 t, %1; cvt.u32.u64 %0, t; }" : "=r"(a) : "l"(p));
    return a;
}
#define CP_ASYNC16(dst, src) \
    asm volatile("cp.async.cg.shared.global [%0], [%1], 16;" :: "r"(dst), "l"(src))
#define CP_COMMIT() asm volatile("cp.async.commit_group;" ::: "memory")
#define CP_WAIT(n)  asm volatile("cp.async.wait_group %0;" :: "n"(n) : "memory")

// =====================================================================
// fp16 mma.sync GEMM:  C[M,N] = alpha * A[M,K] @ B[N,K]^T (+ bias)
// A, B fp16 K-major. Block tile 128x256, BK=32, 256 threads = 8 warps
// (2 M x 4 N), warp tile 64x64 (4 m16 x 8 n8, k16 per MMA).
// 4-stage cp.async pipeline. SMEM rows padded to 40 halves (word
// stride 20 -> fragment banks g*20+t mod 32 all distinct).
// =====================================================================
#define BM 128
#define BN 256
#define BKK 32
#define LDKH 40                              // halves per SMEM row
#define A_TILE_B (128 * LDKH * 2)            // 10240 bytes
#define B_TILE_B (256 * LDKH * 2)            // 20480 bytes
#define STAGE_B  (A_TILE_B + B_TILE_B)       // 30720 bytes
#define NSTAGE 4
#define GEMM_SMEM_BYTES (NSTAGE * STAGE_B)   // 122880

template <bool BIAS, bool HALF_OUT>
__global__ __launch_bounds__(256, 1) void gemm_kernel(
    const __half* __restrict__ Ag, const __half* __restrict__ Bg,
    const float* __restrict__ bias, void* __restrict__ Cg,
    int K, long lda, long ldb, long ldc,
    long sA, long sB, long sC, float alpha)
{
    extern __shared__ char smc[];
    const __half* smh = (const __half*)smc;

    const int tid = threadIdx.x;
    const int wid = tid >> 5;
    const int lid = tid & 31;
    const int wm = wid & 1;          // warp M position (0..1)
    const int wn = wid >> 1;         // warp N position (0..3)
    const int g = lid >> 2;          // 0..7
    const int t = lid & 3;           // 0..3

    const long bm = (long)blockIdx.x * BM;
    const long bn = (long)blockIdx.y * BN;
    const __half* A = Ag + (long)blockIdx.z * sA;
    const __half* B = Bg + (long)blockIdx.z * sB;

    const uint32_t sbase = smem_u32(smc);

    float acc[4][8][4];
#pragma unroll
    for (int mt = 0; mt < 4; ++mt)
#pragma unroll
        for (int nt = 0; nt < 8; ++nt)
#pragma unroll
            for (int c = 0; c < 4; ++c) acc[mt][nt][c] = 0.0f;

    // ---- cp.async one BK=32 chunk into stage s ----
    auto copy_stage = [&](int s, long k0) {
        const uint32_t as = sbase + (uint32_t)(s * STAGE_B);
        const uint32_t bs = as + (uint32_t)A_TILE_B;
#pragma unroll
        for (int it = 0; it < 2; ++it) {
            int c = tid + it * 256;              // 512 chunks: A 128 rows x 4 (8 halves each)
            int m = c >> 2, k8 = (c & 3) << 3;
            CP_ASYNC16(as + (uint32_t)(m * 80 + k8 * 2),
                       &A[(bm + m) * lda + k0 + k8]);
        }
#pragma unroll
        for (int it = 0; it < 4; ++it) {
            int c = tid + it * 256;              // 1024 chunks: B 256 rows x 4
            int n = c >> 2, k8 = (c & 3) << 3;
            CP_ASYNC16(bs + (uint32_t)(n * 80 + k8 * 2),
                       &B[(bn + n) * ldb + k0 + k8]);
        }
    };

    // ---- compute one BK=32 chunk (2 k16 steps) from stage s ----
    auto compute = [&](int s) {
        const __half* As_ = smh + (size_t)s * (STAGE_B / 2);
        const __half* Bs_ = As_ + A_TILE_B / 2;
#pragma unroll
        for (int ks = 0; ks < 2; ++ks) {
            const int kb = ks * 16;
            uint32_t a[4][4], b[8][2];
#pragma unroll
            for (int mt = 0; mt < 4; ++mt) {
                const int m0 = wm * 64 + mt * 16;
                a[mt][0] = *(const uint32_t*)&As_[(m0 + g) * LDKH + kb + 2 * t];
                a[mt][1] = *(const uint32_t*)&As_[(m0 + g + 8) * LDKH + kb + 2 * t];
                a[mt][2] = *(const uint32_t*)&As_[(m0 + g) * LDKH + kb + 2 * t + 8];
                a[mt][3] = *(const uint32_t*)&As_[(m0 + g + 8) * LDKH + kb + 2 * t + 8];
            }
#pragma unroll
            for (int nt = 0; nt < 8; ++nt) {
                const int n0 = wn * 64 + nt * 8;
                b[nt][0] = *(const uint32_t*)&Bs_[(n0 + g) * LDKH + kb + 2 * t];
                b[nt][1] = *(const uint32_t*)&Bs_[(n0 + g) * LDKH + kb + 2 * t + 8];
            }
#pragma unroll
            for (int mt = 0; mt < 4; ++mt)
#pragma unroll
                for (int nt = 0; nt < 8; ++nt)
                    mma_f16(acc[mt][nt], a[mt], b[nt]);
        }
    };

    const int nch = K / BKK;                      // >= 32 here
    copy_stage(0, 0); CP_COMMIT();
    copy_stage(1, BKK); CP_COMMIT();
    copy_stage(2, 2 * BKK); CP_COMMIT();

    for (int i = 0; i < nch; ++i) {
        const int s = i & (NSTAGE - 1);
        if (i + 2 < nch)      { CP_WAIT(2); }
        else if (i + 1 < nch) { CP_WAIT(1); }
        else                  { CP_WAIT(0); }
        __syncthreads();
        if (i + 3 < nch) { copy_stage((i + 3) & (NSTAGE - 1), (long)(i + 3) * BKK); CP_COMMIT(); }
        compute(s);
    }

    // ---- epilogue ----
#pragma unroll
    for (int mt = 0; mt < 4; ++mt) {
        const long mrow = bm + wm * 64 + mt * 16;
#pragma unroll
        for (int nt = 0; nt < 8; ++nt) {
            const long col = bn + wn * 64 + nt * 8 + 2 * t;
            float2 v0, v1;
            v0.x = acc[mt][nt][0] * alpha; v0.y = acc[mt][nt][1] * alpha;
            v1.x = acc[mt][nt][2] * alpha; v1.y = acc[mt][nt][3] * alpha;
            if (BIAS) {
                float b0 = bias[col], b1 = bias[col + 1];
                v0.x += b0; v0.y += b1; v1.x += b0; v1.y += b1;
            }
            if (HALF_OUT) {
                __half* Ch = (__half*)Cg + (long)blockIdx.z * sC;
                *(__half2*)&Ch[(mrow + g) * ldc + col] = __floats2half2_rn(v0.x, v0.y);
                *(__half2*)&Ch[(mrow + g + 8) * ldc + col] = __floats2half2_rn(v1.x, v1.y);
            } else {
                float* Cf = (float*)Cg + (long)blockIdx.z * sC;
                *(float2*)&Cf[(mrow + g) * ldc + col] = v0;
                *(float2*)&Cf[(mrow + g + 8) * ldc + col] = v1;
            }
        }
    }
}

// =====================================================================
// pre-pass: float -> half (float4 granularity)
// =====================================================================
__global__ __launch_bounds__(256) void f2h_kernel(
    const float4* __restrict__ in, __half2* __restrict__ out, long n4)
{
    long i = (long)blockIdx.x * 256 + threadIdx.x;
    if (i < n4) {
        float4 v = in[i];
        out[2 * i]     = __floats2half2_rn(v.x, v.y);
        out[2 * i + 1] = __floats2half2_rn(v.z, v.w);
    }
}

// transpose + convert: out[b][c][r] = half(in[b][r][c])
__global__ __launch_bounds__(256) void transpose_f2h_kernel(
    const float* __restrict__ in, __half* __restrict__ out, int R, int C, long sz)
{
    __shared__ float tbuf[32][33];
    const float* ip = in + (long)blockIdx.z * sz;
    __half* op = out + (long)blockIdx.z * sz;
    int c0 = blockIdx.x * 32, r0 = blockIdx.y * 32;
    int tx = threadIdx.x, ty = threadIdx.y; // 32 x 8
#pragma unroll
    for (int j = 0; j < 32; j += 8) tbuf[ty + j][tx] = ip[(long)(r0 + ty + j) * C + c0 + tx];
    __syncthreads();
#pragma unroll
    for (int j = 0; j < 32; j += 8)
        op[(long)(c0 + ty + j) * R + r0 + tx] = __float2half_rn(tbuf[tx][ty + j]);
}

// =====================================================================
// reductions + softmax/entropy + syntony + layernorm
// =====================================================================
__device__ __forceinline__ float warpReduceSum(float v) {
#pragma unroll
    for (int o = 16; o > 0; o >>= 1) v += __shfl_xor_sync(0xffffffffu, v, o);
    return v;
}
__device__ __forceinline__ float warpReduceMax(float v) {
#pragma unroll
    for (int o = 16; o > 0; o >>= 1) v = fmaxf(v, __shfl_xor_sync(0xffffffffu, v, o));
    return v;
}
__device__ __forceinline__ float blockReduceSum(float v) {
    __shared__ float sh[32];
    int lane = threadIdx.x & 31, w = threadIdx.x >> 5;
    v = warpReduceSum(v);
    if (lane == 0) sh[w] = v;
    __syncthreads();
    int nw = (blockDim.x + 31) >> 5;
    float r = (threadIdx.x < nw) ? sh[threadIdx.x] : 0.0f;
    if (w == 0) r = warpReduceSum(r);
    if (threadIdx.x == 0) sh[0] = r;
    __syncthreads();
    float out = sh[0];
    __syncthreads();
    return out;
}
__device__ __forceinline__ float blockReduceMax(float v) {
    __shared__ float sh[32];
    int lane = threadIdx.x & 31, w = threadIdx.x >> 5;
    v = warpReduceMax(v);
    if (lane == 0) sh[w] = v;
    __syncthreads();
    int nw = (blockDim.x + 31) >> 5;
    float r = (threadIdx.x < nw) ? sh[threadIdx.x] : -FLT_MAX;
    if (w == 0) r = warpReduceMax(r);
    if (threadIdx.x == 0) sh[0] = r;
    __syncthreads();
    float out = sh[0];
    __syncthreads();
    return out;
}

// softmax + entropy: read fp32 scores, write fp16 probs
__global__ __launch_bounds__(256) void softmax_entropy_kernel() {
    const long row = blockIdx.x;
    const float* p = g_scores + row * (long)SEQ;
    __half* ph = g_ph + row * (long)SEQ;
    const int tid = threadIdx.x;
    float x[8];
#pragma unroll
    for (int i = 0; i < 8; ++i) x[i] = p[tid + i * 256];
    float m = -FLT_MAX;
#pragma unroll
    for (int i = 0; i < 8; ++i) m = fmaxf(m, x[i]);
    m = blockReduceMax(m);
    float s = 0.0f;
#pragma unroll
    for (int i = 0; i < 8; ++i) { x[i] = expf(x[i] - m); s += x[i]; }
    s = blockReduceSum(s);
    float inv = 1.0f / s;
    float ent = 0.0f;
#pragma unroll
    for (int i = 0; i < 8; ++i) {
        float pv = x[i] * inv;
        ph[tid + i * 256] = __float2half_rn(pv);
        ent -= pv * logf(pv + EPS_ENT);
    }
    ent = blockReduceSum(ent);
    if (tid == 0) g_rowent[row] = ent;
}

__global__ __launch_bounds__(512) void syntony_kernel(float* __restrict__ out, long tail_off, int tail_cnt) {
    float s = 0.0f;
    const int nrows = BATCH * SEQ;
    for (int i = threadIdx.x; i < nrows; i += 512) s += g_rowent[i];
    s = blockReduceSum(s);
    if (threadIdx.x == 0) {
        float mean = s / (float)nrows;
        float syn = 1.0f - mean / logf((float)SEQ);
        syn = fminf(fmaxf(syn, 0.0f), 1.0f);
        for (int i = 0; i < tail_cnt; ++i) out[tail_off + i] = syn;
    }
}

__global__ __launch_bounds__(256) void layernorm_kernel(
    float* __restrict__ H, const float* __restrict__ gamma, const float* __restrict__ beta)
{
    const long row = blockIdx.x;
    float* h = H + row * (long)DMODEL;
    const int tid = threadIdx.x;
    float x[4];
#pragma unroll
    for (int i = 0; i < 4; ++i) x[i] = h[tid + i * 256];
    float s = x[0] + x[1] + x[2] + x[3];
    s = blockReduceSum(s);
    float mu = s * (1.0f / DMODEL);
    float v = 0.0f;
#pragma unroll
    for (int i = 0; i < 4; ++i) { float d = x[i] - mu; v += d * d; }
    v = blockReduceSum(v);
    float inv = rsqrtf(v * (1.0f / DMODEL) + EPS_LN);
#pragma unroll
    for (int i = 0; i < 4; ++i) {
        int c = tid + i * 256;
        h[c] = (x[i] - mu) * inv * gamma[c] + beta[c];
    }
}

// =====================================================================
// launch
// =====================================================================
extern "C" void kernel_launch(void* const* d_in, const int* in_sizes, int n_in,
                              void* d_out, int out_size) {
    const float* q      = (const float*)d_in[0];
    const float* k      = (const float*)d_in[1];
    const float* v      = (const float*)d_in[2];
    const float* harm_w = (const float*)d_in[3];
    const float* harm_b = (const float*)d_in[4];
    const float* gamma  = (const float*)d_in[5];
    const float* beta   = (const float*)d_in[6];
    float* out = (float*)d_out;

    float *scores;
    __half *qh, *kh, *vth, *wth, *ph, *aoh;
    cudaGetSymbolAddress((void**)&scores, g_scores);
    cudaGetSymbolAddress((void**)&qh, g_qh);
    cudaGetSymbolAddress((void**)&kh, g_kh);
    cudaGetSymbolAddress((void**)&vth, g_vth);
    cudaGetSymbolAddress((void**)&wth, g_wth);
    cudaGetSymbolAddress((void**)&ph, g_ph);
    cudaGetSymbolAddress((void**)&aoh, g_aoh);

    cudaFuncSetAttribute(gemm_kernel<false, false>, cudaFuncAttributeMaxDynamicSharedMemorySize, GEMM_SMEM_BYTES);
    cudaFuncSetAttribute(gemm_kernel<false, true>,  cudaFuncAttributeMaxDynamicSharedMemorySize, GEMM_SMEM_BYTES);
    cudaFuncSetAttribute(gemm_kernel<true, false>,  cudaFuncAttributeMaxDynamicSharedMemorySize, GEMM_SMEM_BYTES);

    const long sQK = (long)SEQ * DMODEL;
    const long sS  = (long)SEQ * SEQ;
    const long BSD = (long)BATCH * SEQ * DMODEL;

    // 0) convert Q,K -> fp16; transpose+convert V,W -> fp16
    {
        long n4 = BSD / 4;
        f2h_kernel<<<(unsigned)((n4 + 255) / 256), 256>>>((const float4*)q, (__half2*)qh, n4);
        f2h_kernel<<<(unsigned)((n4 + 255) / 256), 256>>>((const float4*)k, (__half2*)kh, n4);
        dim3 blk(32, 8);
        transpose_f2h_kernel<<<dim3(DMODEL / 32, DMODEL / 32, 1), blk>>>(harm_w, wth, DMODEL, DMODEL, 0L);
        transpose_f2h_kernel<<<dim3(DMODEL / 32, SEQ / 32, BATCH), blk>>>(v, vth, SEQ, DMODEL, sQK);
    }
    // 1) scores = (Q @ K^T) / 32  -> fp32
    {
        dim3 grid(SEQ / BM, SEQ / BN, BATCH);
        gemm_kernel<false, false><<<grid, 256, GEMM_SMEM_BYTES>>>(
            qh, kh, nullptr, scores, DMODEL, DMODEL, DMODEL, SEQ, sQK, sQK, sS, 1.0f / 32.0f);
    }
    // 2) softmax + row entropy -> fp16 probs
    softmax_entropy_kernel<<<BATCH * SEQ, 256>>>();
    // 3) syntony scalar -> tail of d_out
    {
        int tail = (int)((long)out_size - BSD);
        if (tail > 0) syntony_kernel<<<1, 512>>>(out, BSD, tail);
    }
    // 4) attout = P @ V  (B = V^T fp16, K-major) -> fp16
    {
        dim3 grid(SEQ / BM, DMODEL / BN, BATCH);
        gemm_kernel<false, true><<<grid, 256, GEMM_SMEM_BYTES>>>(
            ph, vth, nullptr, aoh, SEQ, SEQ, SEQ, DMODEL, sS, sQK, sQK, 1.0f);
    }
    // 5) h = attout @ W + b  (B = W^T fp16, K-major) -> d_out fp32
    {
        dim3 grid((BATCH * SEQ) / BM, DMODEL / BN, 1);
        gemm_kernel<true, false><<<grid, 256, GEMM_SMEM_BYTES>>>(
            aoh, wth, harm_b, out, DMODEL, DMODEL, DMODEL, DMODEL, 0L, 0L, 0L, 1.0f);
    }
    // 6) layernorm in-place on d_out
    layernorm_kernel<<<BATCH * SEQ, 256>>>(out, gamma, beta);
}

// round 8
// speedup vs baseline: 1.9826x; 1.0477x over previous
#include <cuda_runtime.h>
#include <cuda_fp16.h>
#include <cstdint>
#include <math.h>
#include <float.h>

// Problem constants
#define BATCH 8
#define SEQ   2048
#define DMODEL 1024
#define EPS_ENT 1e-10f
#define EPS_LN  1e-5f

// ---------------- scratch (allocation-free: __device__ globals) ----------------
__device__ float  g_scores[(size_t)BATCH * SEQ * SEQ];      // 134 MB (fp32 scores)
__device__ __half g_ph[(size_t)BATCH * SEQ * SEQ];          // 67 MB  (fp16 probs)
__device__ __half g_qh[(size_t)BATCH * SEQ * DMODEL];       // 34 MB
__device__ __half g_kh[(size_t)BATCH * SEQ * DMODEL];       // 34 MB
__device__ __half g_vth[(size_t)BATCH * DMODEL * SEQ];      // 34 MB  V^T fp16
__device__ __half g_wth[(size_t)DMODEL * DMODEL];           // 2 MB   W^T fp16
__device__ __half g_aoh[(size_t)BATCH * SEQ * DMODEL];      // 34 MB  attout fp16
__device__ float  g_rowent[(size_t)BATCH * SEQ];

// ---------------- helpers ----------------
__device__ __forceinline__ void mma_f16(float c[4], const uint32_t a[4], const uint32_t b[2]) {
    asm volatile(
        "mma.sync.aligned.m16n8k16.row.col.f32.f16.f16.f32 "
        "{%0,%1,%2,%3}, {%4,%5,%6,%7}, {%8,%9}, {%0,%1,%2,%3};"
        : "+f"(c[0]), "+f"(c[1]), "+f"(c[2]), "+f"(c[3])
        : "r"(a[0]), "r"(a[1]), "r"(a[2]), "r"(a[3]), "r"(b[0]), "r"(b[1]));
}
__device__ __forceinline__ void ldsm_x4(uint32_t& r0, uint32_t& r1, uint32_t& r2, uint32_t& r3,
                                        uint32_t addr) {
    asm volatile("ldmatrix.sync.aligned.m8n8.x4.shared.b16 {%0,%1,%2,%3}, [%4];"
        : "=r"(r0), "=r"(r1), "=r"(r2), "=r"(r3) : "r"(addr));
}
__device__ __forceinline__ uint32_t smem_u32(const void* p) {
    uint32_t a;
    asm("{ .reg .u64 t; cvta.to.shared.u64 t, %1; cvt.u32.u64 %0, t; }" : "=r"(a) : "l"(p));
    return a;
}
#define CP_ASYNC16(dst, src) \
    asm volatile("cp.async.cg.shared.global [%0], [%1], 16;" :: "r"(dst), "l"(src))
#define CP_COMMIT() asm volatile("cp.async.commit_group;" ::: "memory")
#define CP_WAIT(n)  asm volatile("cp.async.wait_group %0;" :: "n"(n) : "memory")

// =====================================================================
// fp16 mma.sync GEMM:  C[M,N] = alpha * A[M,K] @ B[N,K]^T (+ bias)
// Block tile 128x256, BK=32, 256 threads = 8 warps (2 M x 4 N),
// warp tile 64x64. 4-stage cp.async pipeline. ldmatrix.x4 fragment
// loads. SMEM rows: 40 halves (80 B) -> ldmatrix phases conflict-free.
// =====================================================================
#define BM 128
#define BN 256
#define BKK 32
#define LDKH 40                              // halves per SMEM row
#define A_TILE_B (128 * LDKH * 2)            // 10240 bytes
#define B_TILE_B (256 * LDKH * 2)            // 20480 bytes
#define STAGE_B  (A_TILE_B + B_TILE_B)       // 30720 bytes
#define NSTAGE 4
#define GEMM_SMEM_BYTES (NSTAGE * STAGE_B)   // 122880

template <bool BIAS, bool HALF_OUT>
__global__ __launch_bounds__(256, 1) void gemm_kernel(
    const __half* __restrict__ Ag, const __half* __restrict__ Bg,
    const float* __restrict__ bias, void* __restrict__ Cg,
    int K, long lda, long ldb, long ldc,
    long sA, long sB, long sC, float alpha)
{
    extern __shared__ char smc[];

    const int tid = threadIdx.x;
    const int wid = tid >> 5;
    const int lid = tid & 31;
    const int wm = wid & 1;          // warp M position (0..1)
    const int wn = wid >> 1;         // warp N position (0..3)
    const int g = lid >> 2;          // 0..7
    const int t = lid & 3;           // 0..3

    const long bm = (long)blockIdx.x * BM;
    const long bn = (long)blockIdx.y * BN;
    const __half* A = Ag + (long)blockIdx.z * sA;
    const __half* B = Bg + (long)blockIdx.z * sB;

    const uint32_t sbase = smem_u32(smc);

    // ldmatrix lane-address components (in bytes, relative to tile base)
    const int a_row = lid & 15;                 // row within m16 tile
    const int a_koff = (lid >> 4) << 3;         // 0 or 8 halves
    const int b_row = ((lid >> 4) << 3) + (lid & 7);  // row within n16 pair
    const int b_koff = lid & 8;                 // 0 or 8 halves

    float acc[4][8][4];
#pragma unroll
    for (int mt = 0; mt < 4; ++mt)
#pragma unroll
        for (int nt = 0; nt < 8; ++nt)
#pragma unroll
            for (int c = 0; c < 4; ++c) acc[mt][nt][c] = 0.0f;

    // ---- cp.async one BK=32 chunk into stage s ----
    auto copy_stage = [&](int s, long k0) {
        const uint32_t as = sbase + (uint32_t)(s * STAGE_B);
        const uint32_t bs = as + (uint32_t)A_TILE_B;
#pragma unroll
        for (int it = 0; it < 2; ++it) {
            int c = tid + it * 256;              // 512 chunks: A 128 rows x 4 (8 halves)
            int m = c >> 2, k8 = (c & 3) << 3;
            CP_ASYNC16(as + (uint32_t)(m * 80 + k8 * 2),
                       &A[(bm + m) * lda + k0 + k8]);
        }
#pragma unroll
        for (int it = 0; it < 4; ++it) {
            int c = tid + it * 256;              // 1024 chunks: B 256 rows x 4
            int n = c >> 2, k8 = (c & 3) << 3;
            CP_ASYNC16(bs + (uint32_t)(n * 80 + k8 * 2),
                       &B[(bn + n) * ldb + k0 + k8]);
        }
    };

    // ---- compute one BK=32 chunk (2 k16 steps) from stage s ----
    auto compute = [&](int s) {
        const uint32_t as = sbase + (uint32_t)(s * STAGE_B);
        const uint32_t bs = as + (uint32_t)A_TILE_B;
#pragma unroll
        for (int ks = 0; ks < 2; ++ks) {
            const int kb = ks * 16;
            uint32_t a[4][4], b[8][2];
#pragma unroll
            for (int mt = 0; mt < 4; ++mt) {
                const int m0 = wm * 64 + mt * 16;
                ldsm_x4(a[mt][0], a[mt][1], a[mt][2], a[mt][3],
                        as + (uint32_t)((m0 + a_row) * 80 + (kb + a_koff) * 2));
            }
#pragma unroll
            for (int np = 0; np < 4; ++np) {       // pairs of n8 tiles
                const int n0 = wn * 64 + np * 16;
                ldsm_x4(b[2 * np][0], b[2 * np][1], b[2 * np + 1][0], b[2 * np + 1][1],
                        bs + (uint32_t)((n0 + b_row) * 80 + (kb + b_koff) * 2));
            }
#pragma unroll
            for (int mt = 0; mt < 4; ++mt)
#pragma unroll
                for (int nt = 0; nt < 8; ++nt)
                    mma_f16(acc[mt][nt], a[mt], b[nt]);
        }
    };

    const int nch = K / BKK;
    copy_stage(0, 0); CP_COMMIT();
    copy_stage(1, BKK); CP_COMMIT();
    copy_stage(2, 2 * BKK); CP_COMMIT();

    for (int i = 0; i < nch; ++i) {
        const int s = i & (NSTAGE - 1);
        if (i + 2 < nch)      { CP_WAIT(2); }
        else if (i + 1 < nch) { CP_WAIT(1); }
        else                  { CP_WAIT(0); }
        __syncthreads();
        if (i + 3 < nch) { copy_stage((i + 3) & (NSTAGE - 1), (long)(i + 3) * BKK); CP_COMMIT(); }
        compute(s);
    }

    // ---- epilogue ----
#pragma unroll
    for (int mt = 0; mt < 4; ++mt) {
        const long mrow = bm + wm * 64 + mt * 16;
#pragma unroll
        for (int nt = 0; nt < 8; ++nt) {
            const long col = bn + wn * 64 + nt * 8 + 2 * t;
            float2 v0, v1;
            v0.x = acc[mt][nt][0] * alpha; v0.y = acc[mt][nt][1] * alpha;
            v1.x = acc[mt][nt][2] * alpha; v1.y = acc[mt][nt][3] * alpha;
            if (BIAS) {
                float b0 = bias[col], b1 = bias[col + 1];
                v0.x += b0; v0.y += b1; v1.x += b0; v1.y += b1;
            }
            if (HALF_OUT) {
                __half* Ch = (__half*)Cg + (long)blockIdx.z * sC;
                *(__half2*)&Ch[(mrow + g) * ldc + col] = __floats2half2_rn(v0.x, v0.y);
                *(__half2*)&Ch[(mrow + g + 8) * ldc + col] = __floats2half2_rn(v1.x, v1.y);
            } else {
                float* Cf = (float*)Cg + (long)blockIdx.z * sC;
                *(float2*)&Cf[(mrow + g) * ldc + col] = v0;
                *(float2*)&Cf[(mrow + g + 8) * ldc + col] = v1;
            }
        }
    }
}

// =====================================================================
// pre-pass: float -> half (float4 granularity)
// =====================================================================
__global__ __launch_bounds__(256) void f2h_kernel(
    const float4* __restrict__ in, __half2* __restrict__ out, long n4)
{
    long i = (long)blockIdx.x * 256 + threadIdx.x;
    if (i < n4) {
        float4 v = in[i];
        out[2 * i]     = __floats2half2_rn(v.x, v.y);
        out[2 * i + 1] = __floats2half2_rn(v.z, v.w);
    }
}

// transpose + convert: out[b][c][r] = half(in[b][r][c])
__global__ __launch_bounds__(256) void transpose_f2h_kernel(
    const float* __restrict__ in, __half* __restrict__ out, int R, int C, long sz)
{
    __shared__ float tbuf[32][33];
    const float* ip = in + (long)blockIdx.z * sz;
    __half* op = out + (long)blockIdx.z * sz;
    int c0 = blockIdx.x * 32, r0 = blockIdx.y * 32;
    int tx = threadIdx.x, ty = threadIdx.y; // 32 x 8
#pragma unroll
    for (int j = 0; j < 32; j += 8) tbuf[ty + j][tx] = ip[(long)(r0 + ty + j) * C + c0 + tx];
    __syncthreads();
#pragma unroll
    for (int j = 0; j < 32; j += 8)
        op[(long)(c0 + ty + j) * R + r0 + tx] = __float2half_rn(tbuf[tx][ty + j]);
}

// =====================================================================
// reductions + softmax/entropy + syntony + layernorm
// =====================================================================
__device__ __forceinline__ float warpReduceSum(float v) {
#pragma unroll
    for (int o = 16; o > 0; o >>= 1) v += __shfl_xor_sync(0xffffffffu, v, o);
    return v;
}
__device__ __forceinline__ float warpReduceMax(float v) {
#pragma unroll
    for (int o = 16; o > 0; o >>= 1) v = fmaxf(v, __shfl_xor_sync(0xffffffffu, v, o));
    return v;
}
__device__ __forceinline__ float blockReduceSum(float v) {
    __shared__ float sh[32];
    int lane = threadIdx.x & 31, w = threadIdx.x >> 5;
    v = warpReduceSum(v);
    if (lane == 0) sh[w] = v;
    __syncthreads();
    int nw = (blockDim.x + 31) >> 5;
    float r = (threadIdx.x < nw) ? sh[threadIdx.x] : 0.0f;
    if (w == 0) r = warpReduceSum(r);
    if (threadIdx.x == 0) sh[0] = r;
    __syncthreads();
    float out = sh[0];
    __syncthreads();
    return out;
}
__device__ __forceinline__ float blockReduceMax(float v) {
    __shared__ float sh[32];
    int lane = threadIdx.x & 31, w = threadIdx.x >> 5;
    v = warpReduceMax(v);
    if (lane == 0) sh[w] = v;
    __syncthreads();
    int nw = (blockDim.x + 31) >> 5;
    float r = (threadIdx.x < nw) ? sh[threadIdx.x] : -FLT_MAX;
    if (w == 0) r = warpReduceMax(r);
    if (threadIdx.x == 0) sh[0] = r;
    __syncthreads();
    float out = sh[0];
    __syncthreads();
    return out;
}

// softmax + entropy: read fp32 scores, write fp16 probs.
// entropy = log(s) - (1/s) * sum(e^u * u), u = x - m  (identical to
// -sum p log(p+eps) up to O(eps) = 1e-10 per element).
__global__ __launch_bounds__(256) void softmax_entropy_kernel() {
    const long row = blockIdx.x;
    const float* p = g_scores + row * (long)SEQ;
    __half* ph = g_ph + row * (long)SEQ;
    const int tid = threadIdx.x;
    float x[8];
#pragma unroll
    for (int i = 0; i < 8; ++i) x[i] = p[tid + i * 256];
    float m = -FLT_MAX;
#pragma unroll
    for (int i = 0; i < 8; ++i) m = fmaxf(m, x[i]);
    m = blockReduceMax(m);
    float s = 0.0f, w = 0.0f;
#pragma unroll
    for (int i = 0; i < 8; ++i) {
        float u = x[i] - m;
        float e = __expf(u);
        x[i] = e;
        s += e;
        w = fmaf(e, u, w);
    }
    s = blockReduceSum(s);
    w = blockReduceSum(w);
    float inv = 1.0f / s;
#pragma unroll
    for (int i = 0; i < 8; ++i)
        ph[tid + i * 256] = __float2half_rn(x[i] * inv);
    if (tid == 0) g_rowent[row] = __logf(s) - w * inv;
}

__global__ __launch_bounds__(512) void syntony_kernel(float* __restrict__ out, long tail_off, int tail_cnt) {
    float s = 0.0f;
    const int nrows = BATCH * SEQ;
    for (int i = threadIdx.x; i < nrows; i += 512) s += g_rowent[i];
    s = blockReduceSum(s);
    if (threadIdx.x == 0) {
        float mean = s / (float)nrows;
        float syn = 1.0f - mean / logf((float)SEQ);
        syn = fminf(fmaxf(syn, 0.0f), 1.0f);
        for (int i = 0; i < tail_cnt; ++i) out[tail_off + i] = syn;
    }
}

__global__ __launch_bounds__(256) void layernorm_kernel(
    float* __restrict__ H, const float* __restrict__ gamma, const float* __restrict__ beta)
{
    const long row = blockIdx.x;
    float* h = H + row * (long)DMODEL;
    const int tid = threadIdx.x;
    float x[4];
#pragma unroll
    for (int i = 0; i < 4; ++i) x[i] = h[tid + i * 256];
    float s = x[0] + x[1] + x[2] + x[3];
    s = blockReduceSum(s);
    float mu = s * (1.0f / DMODEL);
    float v = 0.0f;
#pragma unroll
    for (int i = 0; i < 4; ++i) { float d = x[i] - mu; v += d * d; }
    v = blockReduceSum(v);
    float inv = rsqrtf(v * (1.0f / DMODEL) + EPS_LN);
#pragma unroll
    for (int i = 0; i < 4; ++i) {
        int c = tid + i * 256;
        h[c] = (x[i] - mu) * inv * gamma[c] + beta[c];
    }
}

// =====================================================================
// launch
// =====================================================================
extern "C" void kernel_launch(void* const* d_in, const int* in_sizes, int n_in,
                              void* d_out, int out_size) {
    const float* q      = (const float*)d_in[0];
    const float* k      = (const float*)d_in[1];
    const float* v      = (const float*)d_in[2];
    const float* harm_w = (const float*)d_in[3];
    const float* harm_b = (const float*)d_in[4];
    const float* gamma  = (const float*)d_in[5];
    const float* beta   = (const float*)d_in[6];
    float* out = (float*)d_out;

    float *scores;
    __half *qh, *kh, *vth, *wth, *ph, *aoh;
    cudaGetSymbolAddress((void**)&scores, g_scores);
    cudaGetSymbolAddress((void**)&qh, g_qh);
    cudaGetSymbolAddress((void**)&kh, g_kh);
    cudaGetSymbolAddress((void**)&vth, g_vth);
    cudaGetSymbolAddress((void**)&wth, g_wth);
    cudaGetSymbolAddress((void**)&ph, g_ph);
    cudaGetSymbolAddress((void**)&aoh, g_aoh);

    cudaFuncSetAttribute(gemm_kernel<false, false>, cudaFuncAttributeMaxDynamicSharedMemorySize, GEMM_SMEM_BYTES);
    cudaFuncSetAttribute(gemm_kernel<false, true>,  cudaFuncAttributeMaxDynamicSharedMemorySize, GEMM_SMEM_BYTES);
    cudaFuncSetAttribute(gemm_kernel<true, false>,  cudaFuncAttributeMaxDynamicSharedMemorySize, GEMM_SMEM_BYTES);

    const long sQK = (long)SEQ * DMODEL;
    const long sS  = (long)SEQ * SEQ;
    const long BSD = (long)BATCH * SEQ * DMODEL;

    // 0) convert Q,K -> fp16; transpose+convert V,W -> fp16
    {
        long n4 = BSD / 4;
        f2h_kernel<<<(unsigned)((n4 + 255) / 256), 256>>>((const float4*)q, (__half2*)qh, n4);
        f2h_kernel<<<(unsigned)((n4 + 255) / 256), 256>>>((const float4*)k, (__half2*)kh, n4);
        dim3 blk(32, 8);
        transpose_f2h_kernel<<<dim3(DMODEL / 32, DMODEL / 32, 1), blk>>>(harm_w, wth, DMODEL, DMODEL, 0L);
        transpose_f2h_kernel<<<dim3(DMODEL / 32, SEQ / 32, BATCH), blk>>>(v, vth, SEQ, DMODEL, sQK);
    }
    // 1) scores = (Q @ K^T) / 32  -> fp32
    {
        dim3 grid(SEQ / BM, SEQ / BN, BATCH);
        gemm_kernel<false, false><<<grid, 256, GEMM_SMEM_BYTES>>>(
            qh, kh, nullptr, scores, DMODEL, DMODEL, DMODEL, SEQ, sQK, sQK, sS, 1.0f / 32.0f);
    }
    // 2) softmax + row entropy -> fp16 probs
    softmax_entropy_kernel<<<BATCH * SEQ, 256>>>();
    // 3) syntony scalar -> tail of d_out
    {
        int tail = (int)((long)out_size - BSD);
        if (tail > 0) syntony_kernel<<<1, 512>>>(out, BSD, tail);
    }
    // 4) attout = P @ V  (B = V^T fp16, K-major) -> fp16
    {
        dim3 grid(SEQ / BM, DMODEL / BN, BATCH);
        gemm_kernel<false, true><<<grid, 256, GEMM_SMEM_BYTES>>>(
            ph, vth, nullptr, aoh, SEQ, SEQ, SEQ, DMODEL, sS, sQK, sQK, 1.0f);
    }
    // 5) h = attout @ W + b  (B = W^T fp16, K-major) -> d_out fp32
    {
        dim3 grid((BATCH * SEQ) / BM, DMODEL / BN, 1);
        gemm_kernel<true, false><<<grid, 256, GEMM_SMEM_BYTES>>>(
            aoh, wth, harm_b, out, DMODEL, DMODEL, DMODEL, DMODEL, 0L, 0L, 0L, 1.0f);
    }
    // 6) layernorm in-place on d_out
    layernorm_kernel<<<BATCH * SEQ, 256>>>(out, gamma, beta);
}

// round 9
// speedup vs baseline: 2.0124x; 1.0150x over previous
#include <cuda_runtime.h>
#include <cuda_fp16.h>
#include <cstdint>
#include <math.h>
#include <float.h>

// Problem constants
#define BATCH 8
#define SEQ   2048
#define DMODEL 1024
#define EPS_ENT 1e-10f
#define EPS_LN  1e-5f

// ---------------- scratch (allocation-free: __device__ globals) ----------------
__device__ float  g_scores[(size_t)BATCH * SEQ * SEQ];      // 134 MB (fp32 scores)
__device__ __half g_ph[(size_t)BATCH * SEQ * SEQ];          // 67 MB  (fp16 probs)
__device__ __half g_qh[(size_t)BATCH * SEQ * DMODEL];       // 34 MB
__device__ __half g_kh[(size_t)BATCH * SEQ * DMODEL];       // 34 MB
__device__ __half g_vth[(size_t)BATCH * DMODEL * SEQ];      // 34 MB  V^T fp16
__device__ __half g_wth[(size_t)DMODEL * DMODEL];           // 2 MB   W^T fp16
__device__ __half g_aoh[(size_t)BATCH * SEQ * DMODEL];      // 34 MB  attout fp16
__device__ float  g_rowent[(size_t)BATCH * SEQ];

// ---------------- helpers ----------------
__device__ __forceinline__ void mma_f16(float c[4], const uint32_t a[4], const uint32_t b[2]) {
    asm volatile(
        "mma.sync.aligned.m16n8k16.row.col.f32.f16.f16.f32 "
        "{%0,%1,%2,%3}, {%4,%5,%6,%7}, {%8,%9}, {%0,%1,%2,%3};"
        : "+f"(c[0]), "+f"(c[1]), "+f"(c[2]), "+f"(c[3])
        : "r"(a[0]), "r"(a[1]), "r"(a[2]), "r"(a[3]), "r"(b[0]), "r"(b[1]));
}
__device__ __forceinline__ void ldsm_x4(uint32_t& r0, uint32_t& r1, uint32_t& r2, uint32_t& r3,
                                        uint32_t addr) {
    asm volatile("ldmatrix.sync.aligned.m8n8.x4.shared.b16 {%0,%1,%2,%3}, [%4];"
        : "=r"(r0), "=r"(r1), "=r"(r2), "=r"(r3) : "r"(addr));
}
__device__ __forceinline__ uint32_t smem_u32(const void* p) {
    uint32_t a;
    asm("{ .reg .u64 t; cvta.to.shared.u64 t, %1; cvt.u32.u64 %0, t; }" : "=r"(a) : "l"(p));
    return a;
}
#define CP_ASYNC16(dst, src) \
    asm volatile("cp.async.cg.shared.global [%0], [%1], 16;" :: "r"(dst), "l"(src))
#define CP_COMMIT() asm volatile("cp.async.commit_group;" ::: "memory")
#define CP_WAIT(n)  asm volatile("cp.async.wait_group %0;" :: "n"(n) : "memory")

// =====================================================================
// fp16 mma.sync GEMM:  C[M,N] = alpha * A[M,K] @ B[N,K]^T (+ bias)
// Block tile 128x256, BK=32, 512 threads = 16 warps (2 M x 8 N),
// warp tile 64x32. 4-stage cp.async pipeline. ldmatrix.x4 fragment
// loads. SMEM rows: 40 halves (80 B) -> ldmatrix phases conflict-free.
// =====================================================================
#define BM 128
#define BN 256
#define BKK 32
#define LDKH 40                              // halves per SMEM row
#define A_TILE_B (128 * LDKH * 2)            // 10240 bytes
#define B_TILE_B (256 * LDKH * 2)            // 20480 bytes
#define STAGE_B  (A_TILE_B + B_TILE_B)       // 30720 bytes
#define NSTAGE 4
#define GEMM_SMEM_BYTES (NSTAGE * STAGE_B)   // 122880
#define NTHR 512

template <bool BIAS, bool HALF_OUT>
__global__ __launch_bounds__(NTHR, 1) void gemm_kernel(
    const __half* __restrict__ Ag, const __half* __restrict__ Bg,
    const float* __restrict__ bias, void* __restrict__ Cg,
    int K, long lda, long ldb, long ldc,
    long sA, long sB, long sC, float alpha)
{
    extern __shared__ char smc[];

    const int tid = threadIdx.x;
    const int wid = tid >> 5;
    const int lid = tid & 31;
    const int wm = wid & 1;          // warp M position (0..1)
    const int wn = wid >> 1;         // warp N position (0..7)
    const int g = lid >> 2;          // 0..7
    const int t = lid & 3;           // 0..3

    const long bm = (long)blockIdx.x * BM;
    const long bn = (long)blockIdx.y * BN;
    const __half* A = Ag + (long)blockIdx.z * sA;
    const __half* B = Bg + (long)blockIdx.z * sB;

    const uint32_t sbase = smem_u32(smc);

    // ldmatrix lane-address components
    const int a_row = lid & 15;                 // row within m16 tile
    const int a_koff = (lid >> 4) << 3;         // 0 or 8 halves
    const int b_row = ((lid >> 4) << 3) + (lid & 7);  // row within n16 pair
    const int b_koff = lid & 8;                 // 0 or 8 halves

    float acc[4][4][4];
#pragma unroll
    for (int mt = 0; mt < 4; ++mt)
#pragma unroll
        for (int nt = 0; nt < 4; ++nt)
#pragma unroll
            for (int c = 0; c < 4; ++c) acc[mt][nt][c] = 0.0f;

    // ---- cp.async one BK=32 chunk into stage s ----
    auto copy_stage = [&](int s, long k0) {
        const uint32_t as = sbase + (uint32_t)(s * STAGE_B);
        const uint32_t bs = as + (uint32_t)A_TILE_B;
        {
            int c = tid;                          // 512 chunks: A 128 rows x 4 (8 halves)
            int m = c >> 2, k8 = (c & 3) << 3;
            CP_ASYNC16(as + (uint32_t)(m * 80 + k8 * 2),
                       &A[(bm + m) * lda + k0 + k8]);
        }
#pragma unroll
        for (int it = 0; it < 2; ++it) {
            int c = tid + it * NTHR;              // 1024 chunks: B 256 rows x 4
            int n = c >> 2, k8 = (c & 3) << 3;
            CP_ASYNC16(bs + (uint32_t)(n * 80 + k8 * 2),
                       &B[(bn + n) * ldb + k0 + k8]);
        }
    };

    // ---- compute one BK=32 chunk (2 k16 steps) from stage s ----
    auto compute = [&](int s) {
        const uint32_t as = sbase + (uint32_t)(s * STAGE_B);
        const uint32_t bs = as + (uint32_t)A_TILE_B;
#pragma unroll
        for (int ks = 0; ks < 2; ++ks) {
            const int kb = ks * 16;
            uint32_t a[4][4], b[4][2];
#pragma unroll
            for (int mt = 0; mt < 4; ++mt) {
                const int m0 = wm * 64 + mt * 16;
                ldsm_x4(a[mt][0], a[mt][1], a[mt][2], a[mt][3],
                        as + (uint32_t)((m0 + a_row) * 80 + (kb + a_koff) * 2));
            }
#pragma unroll
            for (int np = 0; np < 2; ++np) {       // pairs of n8 tiles
                const int n0 = wn * 32 + np * 16;
                ldsm_x4(b[2 * np][0], b[2 * np][1], b[2 * np + 1][0], b[2 * np + 1][1],
                        bs + (uint32_t)((n0 + b_row) * 80 + (kb + b_koff) * 2));
            }
#pragma unroll
            for (int mt = 0; mt < 4; ++mt)
#pragma unroll
                for (int nt = 0; nt < 4; ++nt)
                    mma_f16(acc[mt][nt], a[mt], b[nt]);
        }
    };

    const int nch = K / BKK;
    copy_stage(0, 0); CP_COMMIT();
    copy_stage(1, BKK); CP_COMMIT();
    copy_stage(2, 2 * BKK); CP_COMMIT();

    for (int i = 0; i < nch; ++i) {
        const int s = i & (NSTAGE - 1);
        if (i + 2 < nch)      { CP_WAIT(2); }
        else if (i + 1 < nch) { CP_WAIT(1); }
        else                  { CP_WAIT(0); }
        __syncthreads();
        if (i + 3 < nch) { copy_stage((i + 3) & (NSTAGE - 1), (long)(i + 3) * BKK); CP_COMMIT(); }
        compute(s);
    }

    // ---- epilogue ----
#pragma unroll
    for (int mt = 0; mt < 4; ++mt) {
        const long mrow = bm + wm * 64 + mt * 16;
#pragma unroll
        for (int nt = 0; nt < 4; ++nt) {
            const long col = bn + wn * 32 + nt * 8 + 2 * t;
            float2 v0, v1;
            v0.x = acc[mt][nt][0] * alpha; v0.y = acc[mt][nt][1] * alpha;
            v1.x = acc[mt][nt][2] * alpha; v1.y = acc[mt][nt][3] * alpha;
            if (BIAS) {
                float b0 = bias[col], b1 = bias[col + 1];
                v0.x += b0; v0.y += b1; v1.x += b0; v1.y += b1;
            }
            if (HALF_OUT) {
                __half* Ch = (__half*)Cg + (long)blockIdx.z * sC;
                *(__half2*)&Ch[(mrow + g) * ldc + col] = __floats2half2_rn(v0.x, v0.y);
                *(__half2*)&Ch[(mrow + g + 8) * ldc + col] = __floats2half2_rn(v1.x, v1.y);
            } else {
                float* Cf = (float*)Cg + (long)blockIdx.z * sC;
                *(float2*)&Cf[(mrow + g) * ldc + col] = v0;
                *(float2*)&Cf[(mrow + g + 8) * ldc + col] = v1;
            }
        }
    }
}

// =====================================================================
// pre-pass: float -> half (float4 granularity)
// =====================================================================
__global__ __launch_bounds__(256) void f2h_kernel(
    const float4* __restrict__ in, __half2* __restrict__ out, long n4)
{
    long i = (long)blockIdx.x * 256 + threadIdx.x;
    if (i < n4) {
        float4 v = in[i];
        out[2 * i]     = __floats2half2_rn(v.x, v.y);
        out[2 * i + 1] = __floats2half2_rn(v.z, v.w);
    }
}

// transpose + convert: out[b][c][r] = half(in[b][r][c])
__global__ __launch_bounds__(256) void transpose_f2h_kernel(
    const float* __restrict__ in, __half* __restrict__ out, int R, int C, long sz)
{
    __shared__ float tbuf[32][33];
    const float* ip = in + (long)blockIdx.z * sz;
    __half* op = out + (long)blockIdx.z * sz;
    int c0 = blockIdx.x * 32, r0 = blockIdx.y * 32;
    int tx = threadIdx.x, ty = threadIdx.y; // 32 x 8
#pragma unroll
    for (int j = 0; j < 32; j += 8) tbuf[ty + j][tx] = ip[(long)(r0 + ty + j) * C + c0 + tx];
    __syncthreads();
#pragma unroll
    for (int j = 0; j < 32; j += 8)
        op[(long)(c0 + ty + j) * R + r0 + tx] = __float2half_rn(tbuf[tx][ty + j]);
}

// =====================================================================
// reductions + softmax/entropy + syntony + layernorm
// =====================================================================
__device__ __forceinline__ float warpReduceSum(float v) {
#pragma unroll
    for (int o = 16; o > 0; o >>= 1) v += __shfl_xor_sync(0xffffffffu, v, o);
    return v;
}
__device__ __forceinline__ float warpReduceMax(float v) {
#pragma unroll
    for (int o = 16; o > 0; o >>= 1) v = fmaxf(v, __shfl_xor_sync(0xffffffffu, v, o));
    return v;
}
__device__ __forceinline__ float blockReduceSum(float v) {
    __shared__ float sh[32];
    int lane = threadIdx.x & 31, w = threadIdx.x >> 5;
    v = warpReduceSum(v);
    if (lane == 0) sh[w] = v;
    __syncthreads();
    int nw = (blockDim.x + 31) >> 5;
    float r = (threadIdx.x < nw) ? sh[threadIdx.x] : 0.0f;
    if (w == 0) r = warpReduceSum(r);
    if (threadIdx.x == 0) sh[0] = r;
    __syncthreads();
    float out = sh[0];
    __syncthreads();
    return out;
}
__device__ __forceinline__ float blockReduceMax(float v) {
    __shared__ float sh[32];
    int lane = threadIdx.x & 31, w = threadIdx.x >> 5;
    v = warpReduceMax(v);
    if (lane == 0) sh[w] = v;
    __syncthreads();
    int nw = (blockDim.x + 31) >> 5;
    float r = (threadIdx.x < nw) ? sh[threadIdx.x] : -FLT_MAX;
    if (w == 0) r = warpReduceMax(r);
    if (threadIdx.x == 0) sh[0] = r;
    __syncthreads();
    float out = sh[0];
    __syncthreads();
    return out;
}

// softmax + entropy: read fp32 scores, write fp16 probs.
// entropy = log(s) - (1/s) * sum(e^u * u), u = x - m.
__global__ __launch_bounds__(256) void softmax_entropy_kernel() {
    const long row = blockIdx.x;
    const float* p = g_scores + row * (long)SEQ;
    __half* ph = g_ph + row * (long)SEQ;
    const int tid = threadIdx.x;
    float x[8];
#pragma unroll
    for (int i = 0; i < 8; ++i) x[i] = p[tid + i * 256];
    float m = -FLT_MAX;
#pragma unroll
    for (int i = 0; i < 8; ++i) m = fmaxf(m, x[i]);
    m = blockReduceMax(m);
    float s = 0.0f, w = 0.0f;
#pragma unroll
    for (int i = 0; i < 8; ++i) {
        float u = x[i] - m;
        float e = __expf(u);
        x[i] = e;
        s += e;
        w = fmaf(e, u, w);
    }
    s = blockReduceSum(s);
    w = blockReduceSum(w);
    float inv = 1.0f / s;
#pragma unroll
    for (int i = 0; i < 8; ++i)
        ph[tid + i * 256] = __float2half_rn(x[i] * inv);
    if (tid == 0) g_rowent[row] = __logf(s) - w * inv;
}

__global__ __launch_bounds__(512) void syntony_kernel(float* __restrict__ out, long tail_off, int tail_cnt) {
    float s = 0.0f;
    const int nrows = BATCH * SEQ;
    for (int i = threadIdx.x; i < nrows; i += 512) s += g_rowent[i];
    s = blockReduceSum(s);
    if (threadIdx.x == 0) {
        float mean = s / (float)nrows;
        float syn = 1.0f - mean / logf((float)SEQ);
        syn = fminf(fmaxf(syn, 0.0f), 1.0f);
        for (int i = 0; i < tail_cnt; ++i) out[tail_off + i] = syn;
    }
}

__global__ __launch_bounds__(256) void layernorm_kernel(
    float* __restrict__ H, const float* __restrict__ gamma, const float* __restrict__ beta)
{
    const long row = blockIdx.x;
    float* h = H + row * (long)DMODEL;
    const int tid = threadIdx.x;
    float x[4];
#pragma unroll
    for (int i = 0; i < 4; ++i) x[i] = h[tid + i * 256];
    float s = x[0] + x[1] + x[2] + x[3];
    s = blockReduceSum(s);
    float mu = s * (1.0f / DMODEL);
    float v = 0.0f;
#pragma unroll
    for (int i = 0; i < 4; ++i) { float d = x[i] - mu; v += d * d; }
    v = blockReduceSum(v);
    float inv = rsqrtf(v * (1.0f / DMODEL) + EPS_LN);
#pragma unroll
    for (int i = 0; i < 4; ++i) {
        int c = tid + i * 256;
        h[c] = (x[i] - mu) * inv * gamma[c] + beta[c];
    }
}

// =====================================================================
// launch
// =====================================================================
extern "C" void kernel_launch(void* const* d_in, const int* in_sizes, int n_in,
                              void* d_out, int out_size) {
    const float* q      = (const float*)d_in[0];
    const float* k      = (const float*)d_in[1];
    const float* v      = (const float*)d_in[2];
    const float* harm_w = (const float*)d_in[3];
    const float* harm_b = (const float*)d_in[4];
    const float* gamma  = (const float*)d_in[5];
    const float* beta   = (const float*)d_in[6];
    float* out = (float*)d_out;

    float *scores;
    __half *qh, *kh, *vth, *wth, *ph, *aoh;
    cudaGetSymbolAddress((void**)&scores, g_scores);
    cudaGetSymbolAddress((void**)&qh, g_qh);
    cudaGetSymbolAddress((void**)&kh, g_kh);
    cudaGetSymbolAddress((void**)&vth, g_vth);
    cudaGetSymbolAddress((void**)&wth, g_wth);
    cudaGetSymbolAddress((void**)&ph, g_ph);
    cudaGetSymbolAddress((void**)&aoh, g_aoh);

    cudaFuncSetAttribute(gemm_kernel<false, false>, cudaFuncAttributeMaxDynamicSharedMemorySize, GEMM_SMEM_BYTES);
    cudaFuncSetAttribute(gemm_kernel<false, true>,  cudaFuncAttributeMaxDynamicSharedMemorySize, GEMM_SMEM_BYTES);
    cudaFuncSetAttribute(gemm_kernel<true, false>,  cudaFuncAttributeMaxDynamicSharedMemorySize, GEMM_SMEM_BYTES);

    const long sQK = (long)SEQ * DMODEL;
    const long sS  = (long)SEQ * SEQ;
    const long BSD = (long)BATCH * SEQ * DMODEL;

    // 0) convert Q,K -> fp16; transpose+convert V,W -> fp16
    {
        long n4 = BSD / 4;
        f2h_kernel<<<(unsigned)((n4 + 255) / 256), 256>>>((const float4*)q, (__half2*)qh, n4);
        f2h_kernel<<<(unsigned)((n4 + 255) / 256), 256>>>((const float4*)k, (__half2*)kh, n4);
        dim3 blk(32, 8);
        transpose_f2h_kernel<<<dim3(DMODEL / 32, DMODEL / 32, 1), blk>>>(harm_w, wth, DMODEL, DMODEL, 0L);
        transpose_f2h_kernel<<<dim3(DMODEL / 32, SEQ / 32, BATCH), blk>>>(v, vth, SEQ, DMODEL, sQK);
    }
    // 1) scores = (Q @ K^T) / 32  -> fp32
    {
        dim3 grid(SEQ / BM, SEQ / BN, BATCH);
        gemm_kernel<false, false><<<grid, NTHR, GEMM_SMEM_BYTES>>>(
            qh, kh, nullptr, scores, DMODEL, DMODEL, DMODEL, SEQ, sQK, sQK, sS, 1.0f / 32.0f);
    }
    // 2) softmax + row entropy -> fp16 probs
    softmax_entropy_kernel<<<BATCH * SEQ, 256>>>();
    // 3) syntony scalar -> tail of d_out
    {
        int tail = (int)((long)out_size - BSD);
        if (tail > 0) syntony_kernel<<<1, 512>>>(out, BSD, tail);
    }
    // 4) attout = P @ V  (B = V^T fp16, K-major) -> fp16
    {
        dim3 grid(SEQ / BM, DMODEL / BN, BATCH);
        gemm_kernel<false, true><<<grid, NTHR, GEMM_SMEM_BYTES>>>(
            ph, vth, nullptr, aoh, SEQ, SEQ, SEQ, DMODEL, sS, sQK, sQK, 1.0f);
    }
    // 5) h = attout @ W + b  (B = W^T fp16, K-major) -> d_out fp32
    {
        dim3 grid((BATCH * SEQ) / BM, DMODEL / BN, 1);
        gemm_kernel<true, false><<<grid, NTHR, GEMM_SMEM_BYTES>>>(
            aoh, wth, harm_b, out, DMODEL, DMODEL, DMODEL, DMODEL, 0L, 0L, 0L, 1.0f);
    }
    // 6) layernorm in-place on d_out
    layernorm_kernel<<<BATCH * SEQ, 256>>>(out, gamma, beta);
}

// round 10
// speedup vs baseline: 2.0163x; 1.0019x over previous
#include <cuda_runtime.h>
#include <cuda_fp16.h>
#include <cstdint>
#include <math.h>
#include <float.h>

// Problem constants
#define BATCH 8
#define SEQ   2048
#define DMODEL 1024
#define EPS_ENT 1e-10f
#define EPS_LN  1e-5f
#define NROWS (BATCH * SEQ)
#define NBLK1 8                       // GEMM1 N-tile blocks per row (SEQ/BN)

// ---------------- scratch (allocation-free: __device__ globals) ----------------
__device__ __half g_ph[(size_t)BATCH * SEQ * SEQ];          // 67 MB  unnormalized exp(scores) fp16
__device__ __half g_qh[(size_t)BATCH * SEQ * DMODEL];       // 34 MB
__device__ __half g_kh[(size_t)BATCH * SEQ * DMODEL];       // 34 MB
__device__ __half g_vth[(size_t)BATCH * DMODEL * SEQ];      // 34 MB  V^T fp16
__device__ __half g_wth[(size_t)DMODEL * DMODEL];           // 2 MB   W^T fp16
__device__ __half g_aoh[(size_t)BATCH * SEQ * DMODEL];      // 34 MB  attout fp16
__device__ float  g_psum[(size_t)NROWS * NBLK1];            // partial row sums of e
__device__ float  g_pent[(size_t)NROWS * NBLK1];            // partial row sums of e*x
__device__ float  g_rowinv[(size_t)NROWS];
__device__ float  g_rowent[(size_t)NROWS];

// ---------------- helpers ----------------
__device__ __forceinline__ void mma_f16(float c[4], const uint32_t a[4], const uint32_t b[2]) {
    asm volatile(
        "mma.sync.aligned.m16n8k16.row.col.f32.f16.f16.f32 "
        "{%0,%1,%2,%3}, {%4,%5,%6,%7}, {%8,%9}, {%0,%1,%2,%3};"
        : "+f"(c[0]), "+f"(c[1]), "+f"(c[2]), "+f"(c[3])
        : "r"(a[0]), "r"(a[1]), "r"(a[2]), "r"(a[3]), "r"(b[0]), "r"(b[1]));
}
__device__ __forceinline__ void ldsm_x4(uint32_t& r0, uint32_t& r1, uint32_t& r2, uint32_t& r3,
                                        uint32_t addr) {
    asm volatile("ldmatrix.sync.aligned.m8n8.x4.shared.b16 {%0,%1,%2,%3}, [%4];"
        : "=r"(r0), "=r"(r1), "=r"(r2), "=r"(r3) : "r"(addr));
}
__device__ __forceinline__ uint32_t smem_u32(const void* p) {
    uint32_t a;
    asm("{ .reg .u64 t; cvta.to.shared.u64 t, %1; cvt.u32.u64 %0, t; }" : "=r"(a) : "l"(p));
    return a;
}
#define CP_ASYNC16(dst, src) \
    asm volatile("cp.async.cg.shared.global [%0], [%1], 16;" :: "r"(dst), "l"(src))
#define CP_COMMIT() asm volatile("cp.async.commit_group;" ::: "memory")
#define CP_WAIT(n)  asm volatile("cp.async.wait_group %0;" :: "n"(n) : "memory")

// =====================================================================
// fp16 mma.sync GEMM:  C = A[M,K] @ B[N,K]^T, block tile 128x256,
// BK=32, 512 threads = 16 warps (2 M x 8 N), warp tile 64x32.
// 4-stage cp.async pipeline, ldmatrix.x4, LDKH=40 pad (conflict-free).
// MODE 0: fp32 out, + bias (aux = bias)
// MODE 1: fp16 out = exp(alpha*acc); deterministic per-block row
//         partials of sum(e), sum(e*x) -> psum/pent[row*NBLK1+by]
// MODE 2: fp16 out = alpha*acc * rowinv[row] (aux = rowinv, per batch)
// =====================================================================
#define BM 128
#define BN 256
#define BKK 32
#define LDKH 40
#define A_TILE_B (128 * LDKH * 2)            // 10240 bytes
#define B_TILE_B (256 * LDKH * 2)            // 20480 bytes
#define STAGE_B  (A_TILE_B + B_TILE_B)       // 30720 bytes
#define NSTAGE 4
#define GEMM_SMEM_BYTES (NSTAGE * STAGE_B)   // 122880
#define NTHR 512

template <int MODE>
__global__ __launch_bounds__(NTHR, 1) void gemm_kernel(
    const __half* __restrict__ Ag, const __half* __restrict__ Bg,
    const float* __restrict__ aux, void* __restrict__ Cg,
    float* __restrict__ psum, float* __restrict__ pent,
    int K, long lda, long ldb, long ldc,
    long sA, long sB, long sC, float alpha)
{
    extern __shared__ char smc[];

    const int tid = threadIdx.x;
    const int wid = tid >> 5;
    const int lid = tid & 31;
    const int wm = wid & 1;
    const int wn = wid >> 1;
    const int g = lid >> 2;
    const int t = lid & 3;

    const long bm = (long)blockIdx.x * BM;
    const long bn = (long)blockIdx.y * BN;
    const __half* A = Ag + (long)blockIdx.z * sA;
    const __half* B = Bg + (long)blockIdx.z * sB;

    const uint32_t sbase = smem_u32(smc);

    const int a_row = lid & 15;
    const int a_koff = (lid >> 4) << 3;
    const int b_row = ((lid >> 4) << 3) + (lid & 7);
    const int b_koff = lid & 8;

    float acc[4][4][4];
#pragma unroll
    for (int mt = 0; mt < 4; ++mt)
#pragma unroll
        for (int nt = 0; nt < 4; ++nt)
#pragma unroll
            for (int c = 0; c < 4; ++c) acc[mt][nt][c] = 0.0f;

    auto copy_stage = [&](int s, long k0) {
        const uint32_t as = sbase + (uint32_t)(s * STAGE_B);
        const uint32_t bs = as + (uint32_t)A_TILE_B;
        {
            int c = tid;
            int m = c >> 2, k8 = (c & 3) << 3;
            CP_ASYNC16(as + (uint32_t)(m * 80 + k8 * 2), &A[(bm + m) * lda + k0 + k8]);
        }
#pragma unroll
        for (int it = 0; it < 2; ++it) {
            int c = tid + it * NTHR;
            int n = c >> 2, k8 = (c & 3) << 3;
            CP_ASYNC16(bs + (uint32_t)(n * 80 + k8 * 2), &B[(bn + n) * ldb + k0 + k8]);
        }
    };

    auto compute = [&](int s) {
        const uint32_t as = sbase + (uint32_t)(s * STAGE_B);
        const uint32_t bs = as + (uint32_t)A_TILE_B;
#pragma unroll
        for (int ks = 0; ks < 2; ++ks) {
            const int kb = ks * 16;
            uint32_t a[4][4], b[4][2];
#pragma unroll
            for (int mt = 0; mt < 4; ++mt) {
                const int m0 = wm * 64 + mt * 16;
                ldsm_x4(a[mt][0], a[mt][1], a[mt][2], a[mt][3],
                        as + (uint32_t)((m0 + a_row) * 80 + (kb + a_koff) * 2));
            }
#pragma unroll
            for (int np = 0; np < 2; ++np) {
                const int n0 = wn * 32 + np * 16;
                ldsm_x4(b[2 * np][0], b[2 * np][1], b[2 * np + 1][0], b[2 * np + 1][1],
                        bs + (uint32_t)((n0 + b_row) * 80 + (kb + b_koff) * 2));
            }
#pragma unroll
            for (int mt = 0; mt < 4; ++mt)
#pragma unroll
                for (int nt = 0; nt < 4; ++nt)
                    mma_f16(acc[mt][nt], a[mt], b[nt]);
        }
    };

    const int nch = K / BKK;
    copy_stage(0, 0); CP_COMMIT();
    copy_stage(1, BKK); CP_COMMIT();
    copy_stage(2, 2 * BKK); CP_COMMIT();

    for (int i = 0; i < nch; ++i) {
        const int s = i & (NSTAGE - 1);
        if (i + 2 < nch)      { CP_WAIT(2); }
        else if (i + 1 < nch) { CP_WAIT(1); }
        else                  { CP_WAIT(0); }
        __syncthreads();
        if (i + 3 < nch) { copy_stage((i + 3) & (NSTAGE - 1), (long)(i + 3) * BKK); CP_COMMIT(); }
        compute(s);
    }

    // ================= epilogues =================
    if (MODE == 1) {
        // exp + deterministic row-partial stats, then fp16 store
        float* sp = (float*)smc;          // [128][8] sum(e)
        float* se = sp + 128 * 8;         // [128][8] sum(e*x)
        __syncthreads();                  // done with pipeline smem
#pragma unroll
        for (int mt = 0; mt < 4; ++mt) {
            float pe0 = 0.f, pe1 = 0.f, px0 = 0.f, px1 = 0.f;
#pragma unroll
            for (int nt = 0; nt < 4; ++nt) {
                float x0 = acc[mt][nt][0] * alpha, x1 = acc[mt][nt][1] * alpha;
                float x2 = acc[mt][nt][2] * alpha, x3 = acc[mt][nt][3] * alpha;
                float e0 = __expf(x0), e1 = __expf(x1);
                float e2 = __expf(x2), e3 = __expf(x3);
                pe0 += e0 + e1;  px0 += e0 * x0 + e1 * x1;
                pe1 += e2 + e3;  px1 += e2 * x2 + e3 * x3;
                acc[mt][nt][0] = e0; acc[mt][nt][1] = e1;
                acc[mt][nt][2] = e2; acc[mt][nt][3] = e3;
            }
#pragma unroll
            for (int o = 1; o < 4; o <<= 1) {      // quad reduce over t
                pe0 += __shfl_xor_sync(0xffffffffu, pe0, o);
                pe1 += __shfl_xor_sync(0xffffffffu, pe1, o);
                px0 += __shfl_xor_sync(0xffffffffu, px0, o);
                px1 += __shfl_xor_sync(0xffffffffu, px1, o);
            }
            if (t == 0) {
                int r0 = wm * 64 + mt * 16 + g;
                sp[r0 * 8 + wn] = pe0;       se[r0 * 8 + wn] = px0;
                sp[(r0 + 8) * 8 + wn] = pe1; se[(r0 + 8) * 8 + wn] = px1;
            }
        }
        __syncthreads();
        if (tid < 256) {
            int r = tid & 127, which = tid >> 7;
            const float* arr = which ? se : sp;
            float s = 0.f;
#pragma unroll
            for (int j = 0; j < 8; ++j) s += arr[r * 8 + j];
            long gr = (long)blockIdx.z * SEQ + bm + r;
            (which ? pent : psum)[gr * NBLK1 + blockIdx.y] = s;
        }
        __half* Ch = (__half*)Cg + (long)blockIdx.z * sC;
#pragma unroll
        for (int mt = 0; mt < 4; ++mt) {
            const long mrow = bm + wm * 64 + mt * 16;
#pragma unroll
            for (int nt = 0; nt < 4; ++nt) {
                const long col = bn + wn * 32 + nt * 8 + 2 * t;
                *(__half2*)&Ch[(mrow + g) * ldc + col] =
                    __floats2half2_rn(acc[mt][nt][0], acc[mt][nt][1]);
                *(__half2*)&Ch[(mrow + g + 8) * ldc + col] =
                    __floats2half2_rn(acc[mt][nt][2], acc[mt][nt][3]);
            }
        }
    } else if (MODE == 2) {
        const float* rinv = aux + (long)blockIdx.z * SEQ;
        __half* Ch = (__half*)Cg + (long)blockIdx.z * sC;
#pragma unroll
        for (int mt = 0; mt < 4; ++mt) {
            const long mrow = bm + wm * 64 + mt * 16;
            const float i0 = rinv[mrow + g];
            const float i1 = rinv[mrow + g + 8];
#pragma unroll
            for (int nt = 0; nt < 4; ++nt) {
                const long col = bn + wn * 32 + nt * 8 + 2 * t;
                *(__half2*)&Ch[(mrow + g) * ldc + col] =
                    __floats2half2_rn(acc[mt][nt][0] * i0, acc[mt][nt][1] * i0);
                *(__half2*)&Ch[(mrow + g + 8) * ldc + col] =
                    __floats2half2_rn(acc[mt][nt][2] * i1, acc[mt][nt][3] * i1);
            }
        }
    } else {
        float* Cf = (float*)Cg + (long)blockIdx.z * sC;
#pragma unroll
        for (int mt = 0; mt < 4; ++mt) {
            const long mrow = bm + wm * 64 + mt * 16;
#pragma unroll
            for (int nt = 0; nt < 4; ++nt) {
                const long col = bn + wn * 32 + nt * 8 + 2 * t;
                float2 v0, v1;
                v0.x = acc[mt][nt][0] * alpha; v0.y = acc[mt][nt][1] * alpha;
                v1.x = acc[mt][nt][2] * alpha; v1.y = acc[mt][nt][3] * alpha;
                float b0 = aux[col], b1 = aux[col + 1];
                v0.x += b0; v0.y += b1; v1.x += b0; v1.y += b1;
                *(float2*)&Cf[(mrow + g) * ldc + col] = v0;
                *(float2*)&Cf[(mrow + g + 8) * ldc + col] = v1;
            }
        }
    }
}

// =====================================================================
// rowstat: combine 8 partials per row -> rowinv, rowent
// =====================================================================
__global__ __launch_bounds__(256) void rowstat_kernel() {
    int r = blockIdx.x * 256 + threadIdx.x;
    if (r < NROWS) {
        float s = 0.f, w = 0.f;
#pragma unroll
        for (int j = 0; j < NBLK1; ++j) { s += g_psum[r * NBLK1 + j]; w += g_pent[r * NBLK1 + j]; }
        g_rowinv[r] = 1.0f / s;
        g_rowent[r] = __logf(s) - w / s;
    }
}

// =====================================================================
// pre-pass: float -> half, 4 float4 per thread (ILP)
// =====================================================================
__global__ __launch_bounds__(256) void f2h_kernel(
    const float4* __restrict__ in, __half2* __restrict__ out, long n4)
{
    long base = (long)blockIdx.x * 1024 + threadIdx.x;
#pragma unroll
    for (int j = 0; j < 4; ++j) {
        long i = base + j * 256;
        if (i < n4) {
            float4 v = in[i];
            out[2 * i]     = __floats2half2_rn(v.x, v.y);
            out[2 * i + 1] = __floats2half2_rn(v.z, v.w);
        }
    }
}

// transpose + convert: out[b][c][r] = half(in[b][r][c])
__global__ __launch_bounds__(256) void transpose_f2h_kernel(
    const float* __restrict__ in, __half* __restrict__ out, int R, int C, long sz)
{
    __shared__ float tbuf[32][33];
    const float* ip = in + (long)blockIdx.z * sz;
    __half* op = out + (long)blockIdx.z * sz;
    int c0 = blockIdx.x * 32, r0 = blockIdx.y * 32;
    int tx = threadIdx.x, ty = threadIdx.y; // 32 x 8
#pragma unroll
    for (int j = 0; j < 32; j += 8) tbuf[ty + j][tx] = ip[(long)(r0 + ty + j) * C + c0 + tx];
    __syncthreads();
#pragma unroll
    for (int j = 0; j < 32; j += 8)
        op[(long)(c0 + ty + j) * R + r0 + tx] = __float2half_rn(tbuf[tx][ty + j]);
}

// =====================================================================
// reductions + syntony + layernorm
// =====================================================================
__device__ __forceinline__ float warpReduceSum(float v) {
#pragma unroll
    for (int o = 16; o > 0; o >>= 1) v += __shfl_xor_sync(0xffffffffu, v, o);
    return v;
}
__device__ __forceinline__ float blockReduceSum(float v) {
    __shared__ float sh[32];
    int lane = threadIdx.x & 31, w = threadIdx.x >> 5;
    v = warpReduceSum(v);
    if (lane == 0) sh[w] = v;
    __syncthreads();
    int nw = (blockDim.x + 31) >> 5;
    float r = (threadIdx.x < nw) ? sh[threadIdx.x] : 0.0f;
    if (w == 0) r = warpReduceSum(r);
    if (threadIdx.x == 0) sh[0] = r;
    __syncthreads();
    float out = sh[0];
    __syncthreads();
    return out;
}

__global__ __launch_bounds__(512) void syntony_kernel(float* __restrict__ out, long tail_off, int tail_cnt) {
    float s = 0.0f;
    for (int i = threadIdx.x; i < NROWS; i += 512) s += g_rowent[i];
    s = blockReduceSum(s);
    if (threadIdx.x == 0) {
        float mean = s / (float)NROWS;
        float syn = 1.0f - mean / logf((float)SEQ);
        syn = fminf(fmaxf(syn, 0.0f), 1.0f);
        for (int i = 0; i < tail_cnt; ++i) out[tail_off + i] = syn;
    }
}

__global__ __launch_bounds__(256) void layernorm_kernel(
    float* __restrict__ H, const float* __restrict__ gamma, const float* __restrict__ beta)
{
    const long row = blockIdx.x;
    float* h = H + row * (long)DMODEL;
    const int tid = threadIdx.x;
    float x[4];
#pragma unroll
    for (int i = 0; i < 4; ++i) x[i] = h[tid + i * 256];
    float s = x[0] + x[1] + x[2] + x[3];
    s = blockReduceSum(s);
    float mu = s * (1.0f / DMODEL);
    float v = 0.0f;
#pragma unroll
    for (int i = 0; i < 4; ++i) { float d = x[i] - mu; v += d * d; }
    v = blockReduceSum(v);
    float inv = rsqrtf(v * (1.0f / DMODEL) + EPS_LN);
#pragma unroll
    for (int i = 0; i < 4; ++i) {
        int c = tid + i * 256;
        h[c] = (x[i] - mu) * inv * gamma[c] + beta[c];
    }
}

// =====================================================================
// launch
// =====================================================================
extern "C" void kernel_launch(void* const* d_in, const int* in_sizes, int n_in,
                              void* d_out, int out_size) {
    const float* q      = (const float*)d_in[0];
    const float* k      = (const float*)d_in[1];
    const float* v      = (const float*)d_in[2];
    const float* harm_w = (const float*)d_in[3];
    const float* harm_b = (const float*)d_in[4];
    const float* gamma  = (const float*)d_in[5];
    const float* beta   = (const float*)d_in[6];
    float* out = (float*)d_out;

    __half *qh, *kh, *vth, *wth, *ph, *aoh;
    float *psum, *pent, *rowinv;
    cudaGetSymbolAddress((void**)&qh, g_qh);
    cudaGetSymbolAddress((void**)&kh, g_kh);
    cudaGetSymbolAddress((void**)&vth, g_vth);
    cudaGetSymbolAddress((void**)&wth, g_wth);
    cudaGetSymbolAddress((void**)&ph, g_ph);
    cudaGetSymbolAddress((void**)&aoh, g_aoh);
    cudaGetSymbolAddress((void**)&psum, g_psum);
    cudaGetSymbolAddress((void**)&pent, g_pent);
    cudaGetSymbolAddress((void**)&rowinv, g_rowinv);

    cudaFuncSetAttribute(gemm_kernel<0>, cudaFuncAttributeMaxDynamicSharedMemorySize, GEMM_SMEM_BYTES);
    cudaFuncSetAttribute(gemm_kernel<1>, cudaFuncAttributeMaxDynamicSharedMemorySize, GEMM_SMEM_BYTES);
    cudaFuncSetAttribute(gemm_kernel<2>, cudaFuncAttributeMaxDynamicSharedMemorySize, GEMM_SMEM_BYTES);

    const long sQK = (long)SEQ * DMODEL;
    const long sS  = (long)SEQ * SEQ;
    const long BSD = (long)BATCH * SEQ * DMODEL;

    // 0) convert Q,K -> fp16; transpose+convert V,W -> fp16
    {
        long n4 = BSD / 4;
        f2h_kernel<<<(unsigned)((n4 + 1023) / 1024), 256>>>((const float4*)q, (__half2*)qh, n4);
        f2h_kernel<<<(unsigned)((n4 + 1023) / 1024), 256>>>((const float4*)k, (__half2*)kh, n4);
        dim3 blk(32, 8);
        transpose_f2h_kernel<<<dim3(DMODEL / 32, DMODEL / 32, 1), blk>>>(harm_w, wth, DMODEL, DMODEL, 0L);
        transpose_f2h_kernel<<<dim3(DMODEL / 32, SEQ / 32, BATCH), blk>>>(v, vth, SEQ, DMODEL, sQK);
    }
    // 1) expP = exp(QK^T/32) fp16 + row partial stats (fused softmax, no max-sub)
    {
        dim3 grid(SEQ / BM, SEQ / BN, BATCH);
        gemm_kernel<1><<<grid, NTHR, GEMM_SMEM_BYTES>>>(
            qh, kh, nullptr, ph, psum, pent,
            DMODEL, DMODEL, DMODEL, SEQ, sQK, sQK, sS, 1.0f / 32.0f);
    }
    // 2) row stats: rowinv = 1/s, rowent = log(s) - w/s
    rowstat_kernel<<<NROWS / 256, 256>>>();
    // 3) syntony scalar -> tail of d_out
    {
        int tail = (int)((long)out_size - BSD);
        if (tail > 0) syntony_kernel<<<1, 512>>>(out, BSD, tail);
    }
    // 4) attout = (expP @ V) * rowinv  -> fp16
    {
        dim3 grid(SEQ / BM, DMODEL / BN, BATCH);
        gemm_kernel<2><<<grid, NTHR, GEMM_SMEM_BYTES>>>(
            ph, vth, rowinv, aoh, nullptr, nullptr,
            SEQ, SEQ, SEQ, DMODEL, sS, sQK, sQK, 1.0f);
    }
    // 5) h = attout @ W + b -> d_out fp32
    {
        dim3 grid((BATCH * SEQ) / BM, DMODEL / BN, 1);
        gemm_kernel<0><<<grid, NTHR, GEMM_SMEM_BYTES>>>(
            aoh, wth, harm_b, out, nullptr, nullptr,
            DMODEL, DMODEL, DMODEL, DMODEL, 0L, 0L, 0L, 1.0f);
    }
    // 6) layernorm in-place on d_out
    layernorm_kernel<<<BATCH * SEQ, 256>>>(out, gamma, beta);
}